// round 2
// baseline (speedup 1.0000x reference)
#include <cuda_runtime.h>
#include <math.h>

// Problem constants
#define Bv   8
#define Nv   784
#define Cv   768
#define Hv   8
#define Dv   96
#define NNv  614656            // 784*784
#define BNNv 4917248           // B*N*N
#define BHND 4816896           // B*H*N*D = B*N*C
#define SCALEF 0.1020620726159657495f   // 96^-0.5
#define BN_EPS 1e-5

// ---------------- scratch (static device memory; no allocs allowed) -------
__device__ float  g_qh[BHND];
__device__ float  g_kh[BHND];
__device__ float  g_vh[BHND];
__device__ float  g_attn [39337984];   // (B,H,N,N)  S -> P (softmax, in place)
__device__ float  g_attn2[39337984];   // (B,O,N,N)  mixed A
__device__ float  g_xcat[BHND];        // (B,N,C) pre-projection
__device__ float  g_colsum[Bv*Hv*Dv];  // sum_m v[b,h,m,d]
__device__ double g_stats[16];         // [0..7]=sum(A-mu), [8..15]=sum((A-mu)^2)
__device__ float  g_bn[16];            // [0..7]=a_o, [8..15]=c_o

// ---------------- zero stats ---------------------------------------------
__global__ void zero_stats_kernel() {
    int t = threadIdx.x;
    if (t < 16) g_stats[t] = 0.0;
}

// ---------------- per-token 3x3 conv QKV projection ----------------------
// grid: (B*N tokens, 3 tensors), block 256
__global__ void __launch_bounds__(256) conv_qkv_kernel(
        const float* __restrict__ q,
        const float* __restrict__ k,
        const float* __restrict__ v,
        const float* __restrict__ Wq,
        const float* __restrict__ Wk,
        const float* __restrict__ Wv) {
    __shared__ float xs[768];
    __shared__ float ws[81];
    const int t     = blockIdx.x;          // token = b*N + n
    const int which = blockIdx.y;
    const float* in = (which == 0) ? q : (which == 1) ? k : v;
    const float* W  = (which == 0) ? Wq : (which == 1) ? Wk : Wv;
    float* out      = (which == 0) ? g_qh : (which == 1) ? g_kh : g_vh;
    const int tid = threadIdx.x;

    const float* xin = in + (size_t)t * 768;
    for (int i = tid; i < 768; i += 256) xs[i] = xin[i];
    if (tid < 81) ws[tid] = W[tid];
    __syncthreads();

    const int b = t / Nv, n = t % Nv;
    #pragma unroll
    for (int r = 0; r < 3; r++) {
        const int c   = tid + 256 * r;
        const int co  = c >> 8;            // output conv channel (0..2)
        const int rem = c & 255;
        const int i   = rem >> 4, j = rem & 15;
        float acc = 0.f;
        #pragma unroll
        for (int ci = 0; ci < 3; ci++) {
            #pragma unroll
            for (int di = 0; di < 3; di++) {
                const int ii = i + di - 1;
                if (ii < 0 || ii > 15) continue;
                #pragma unroll
                for (int dj = 0; dj < 3; dj++) {
                    const int jj = j + dj - 1;
                    if (jj < 0 || jj > 15) continue;
                    acc += xs[ci * 256 + ii * 16 + jj] * ws[co * 27 + ci * 9 + di * 3 + dj];
                }
            }
        }
        const int h = c / 96, d = c % 96;
        out[((size_t)(b * Hv + h) * Nv + n) * Dv + d] = acc;
    }
}

// ---------------- column sums of V ----------------------------------------
// grid: B*H blocks, 384 threads = 96 d-lanes x 4 m-slices
__global__ void __launch_bounds__(384) colsum_v_kernel() {
    __shared__ float part[4][96];
    const int bh   = blockIdx.x;
    const int d    = threadIdx.x % 96;
    const int slc  = threadIdx.x / 96;
    const float* vp = g_vh + (size_t)bh * Nv * Dv + d;
    float s = 0.f;
    for (int m = slc; m < Nv; m += 4) s += vp[(size_t)m * Dv];
    part[slc][d] = s;
    __syncthreads();
    if (slc == 0)
        g_colsum[bh * Dv + d] = part[0][d] + part[1][d] + part[2][d] + part[3][d];
}

// ---------------- generic tiled GEMM:  C = alpha * A * B^T (+bias[col]) ---
// A: M x K row-major (lda), B: N x K row-major (ldb). 64x64x16, 256 threads.
__global__ void __launch_bounds__(256) gemm_tn_kernel(
                               const float* __restrict__ A,
                               const float* __restrict__ Bm,
                               float* __restrict__ C,
                               int M, int Nn, int K,
                               int lda, int ldb, int ldc,
                               long sA, long sB, long sC,
                               float alpha, const float* __restrict__ bias) {
    __shared__ float As[16][68];
    __shared__ float Bs[16][68];
    const int z = blockIdx.z;
    A  += (size_t)z * sA;
    Bm += (size_t)z * sB;
    C  += (size_t)z * sC;
    const int m0 = blockIdx.y * 64, n0 = blockIdx.x * 64;
    const int tid = threadIdx.x;
    const int tx = tid & 15, ty = tid >> 4;
    const int lr = tid >> 2, lq = tid & 3;

    float acc[4][4];
    #pragma unroll
    for (int i = 0; i < 4; i++)
        #pragma unroll
        for (int j = 0; j < 4; j++) acc[i][j] = 0.f;

    for (int k0 = 0; k0 < K; k0 += 16) {
        float4 va = make_float4(0.f, 0.f, 0.f, 0.f);
        if (m0 + lr < M)
            va = *(const float4*)(A + (size_t)(m0 + lr) * lda + k0 + lq * 4);
        As[lq * 4 + 0][lr] = va.x;
        As[lq * 4 + 1][lr] = va.y;
        As[lq * 4 + 2][lr] = va.z;
        As[lq * 4 + 3][lr] = va.w;

        float4 vb = make_float4(0.f, 0.f, 0.f, 0.f);
        if (n0 + lr < Nn)
            vb = *(const float4*)(Bm + (size_t)(n0 + lr) * ldb + k0 + lq * 4);
        Bs[lq * 4 + 0][lr] = vb.x;
        Bs[lq * 4 + 1][lr] = vb.y;
        Bs[lq * 4 + 2][lr] = vb.z;
        Bs[lq * 4 + 3][lr] = vb.w;
        __syncthreads();

        #pragma unroll
        for (int kk = 0; kk < 16; kk++) {
            const float4 a  = *(const float4*)(&As[kk][ty * 4]);
            const float4 bq = *(const float4*)(&Bs[kk][tx * 4]);
            acc[0][0] += a.x * bq.x; acc[0][1] += a.x * bq.y; acc[0][2] += a.x * bq.z; acc[0][3] += a.x * bq.w;
            acc[1][0] += a.y * bq.x; acc[1][1] += a.y * bq.y; acc[1][2] += a.y * bq.z; acc[1][3] += a.y * bq.w;
            acc[2][0] += a.z * bq.x; acc[2][1] += a.z * bq.y; acc[2][2] += a.z * bq.z; acc[2][3] += a.z * bq.w;
            acc[3][0] += a.w * bq.x; acc[3][1] += a.w * bq.y; acc[3][2] += a.w * bq.z; acc[3][3] += a.w * bq.w;
        }
        __syncthreads();
    }

    #pragma unroll
    for (int i = 0; i < 4; i++) {
        const int row = m0 + ty * 4 + i;
        if (row < M) {
            #pragma unroll
            for (int j = 0; j < 4; j++) {
                const int col = n0 + tx * 4 + j;
                if (col < Nn) {
                    float vv = acc[i][j] * alpha;
                    if (bias) vv += bias[col];
                    C[(size_t)row * ldc + col] = vv;
                }
            }
        }
    }
}

// ---------------- row softmax over last dim (in place on g_attn) ----------
__global__ void __launch_bounds__(256) softmax_kernel() {
    __shared__ float buf[Nv];
    __shared__ float red[8];
    const size_t row = blockIdx.x;
    float* p = g_attn + row * Nv;
    const int tid = threadIdx.x;

    float lmax = -1e30f;
    for (int i = tid; i < Nv; i += 256) {
        const float v = p[i];
        buf[i] = v;
        lmax = fmaxf(lmax, v);
    }
    #pragma unroll
    for (int s = 16; s; s >>= 1) lmax = fmaxf(lmax, __shfl_xor_sync(0xffffffffu, lmax, s));
    if ((tid & 31) == 0) red[tid >> 5] = lmax;
    __syncthreads();
    float rmax = red[0];
    #pragma unroll
    for (int w = 1; w < 8; w++) rmax = fmaxf(rmax, red[w]);
    __syncthreads();

    float lsum = 0.f;
    for (int i = tid; i < Nv; i += 256) {
        const float e = __expf(buf[i] - rmax);
        buf[i] = e;
        lsum += e;
    }
    #pragma unroll
    for (int s = 16; s; s >>= 1) lsum += __shfl_xor_sync(0xffffffffu, lsum, s);
    if ((tid & 31) == 0) red[tid >> 5] = lsum;
    __syncthreads();
    float tot = 0.f;
    #pragma unroll
    for (int w = 0; w < 8; w++) tot += red[w];
    const float inv = 1.f / tot;

    for (int i = tid; i < Nv; i += 256) p[i] = buf[i] * inv;
}

// ---------------- cross-head mix + BN stats (centered on analytic mu) -----
// grid: BNNv/256 blocks, 256 threads; thread t handles one (b, n, m)
__global__ void __launch_bounds__(256) mix_stats_kernel(
                                 const float* __restrict__ Wre,
                                 const float* __restrict__ bre) {
    __shared__ float sW[64];
    __shared__ float sb[8];
    __shared__ float smu[8];
    __shared__ float part[8][16];
    const int tid = threadIdx.x;
    if (tid < 64) sW[tid] = Wre[tid];
    if (tid < 8)  sb[tid] = bre[tid];
    __syncthreads();
    if (tid < 8) {
        float s = 0.f;
        #pragma unroll
        for (int h = 0; h < 8; h++) s += sW[tid * 8 + h];
        smu[tid] = s * (1.0f / (float)Nv) + sb[tid];   // exact softmax row-sum = 1
    }
    __syncthreads();

    const int t = blockIdx.x * 256 + tid;              // < BNNv exactly
    const int b = t / NNv;
    const int r = t - b * NNv;
    const float* base = g_attn + (size_t)b * Hv * NNv + r;
    float pr[8];
    #pragma unroll
    for (int h = 0; h < 8; h++) pr[h] = __ldg(base + (size_t)h * NNv);

    float* ob = g_attn2 + (size_t)b * Hv * NNv + r;
    float sd[8], sq[8];
    #pragma unroll
    for (int o = 0; o < 8; o++) {
        float a = sb[o];
        #pragma unroll
        for (int h = 0; h < 8; h++) a += sW[o * 8 + h] * pr[h];
        ob[(size_t)o * NNv] = a;
        const float dd = a - smu[o];
        sd[o] = dd;
        sq[o] = dd * dd;
    }
    #pragma unroll
    for (int o = 0; o < 8; o++) {
        #pragma unroll
        for (int s = 16; s; s >>= 1) {
            sd[o] += __shfl_xor_sync(0xffffffffu, sd[o], s);
            sq[o] += __shfl_xor_sync(0xffffffffu, sq[o], s);
        }
    }
    if ((tid & 31) == 0) {
        const int w = tid >> 5;
        #pragma unroll
        for (int o = 0; o < 8; o++) {
            part[w][o]     = sd[o];
            part[w][8 + o] = sq[o];
        }
    }
    __syncthreads();
    if (tid < 16) {
        float s = 0.f;
        #pragma unroll
        for (int w = 0; w < 8; w++) s += part[w][tid];
        atomicAdd(&g_stats[tid], (double)s);
    }
}

// ---------------- finalize BN scalars -------------------------------------
__global__ void bn_finalize_kernel(const float* __restrict__ Wre,
                                   const float* __restrict__ bre,
                                   const float* __restrict__ gamma,
                                   const float* __restrict__ beta) {
    const int o = threadIdx.x;
    if (o >= 8) return;
    const double cnt = (double)BNNv;
    float s = 0.f;
    #pragma unroll
    for (int h = 0; h < 8; h++) s += Wre[o * 8 + h];
    const double mu   = (double)s / (double)Nv + (double)bre[o];
    const double sd   = g_stats[o];
    const double sq   = g_stats[8 + o];
    const double mean = mu + sd / cnt;
    const double var  = sq / cnt - (sd / cnt) * (sd / cnt);
    const float a = gamma[o] * (float)(1.0 / sqrt(var + (double)BN_EPS));
    const float c = beta[o] - a * (float)mean;
    g_bn[o]     = a;
    g_bn[8 + o] = c;
}

// ---------------- AV GEMM (NN) with BN-affine epilogue, scatter to xcat ---
// per (b,o): Y[n,d] = a_o * (A @ V)[n,d] + c_o * colsumV[d]
__global__ void __launch_bounds__(256) gemm_av_kernel() {
    __shared__ float As[16][68];
    __shared__ float Bs[16][68];
    const int bh = blockIdx.z;
    const int b = bh >> 3, o = bh & 7;
    const float* A  = g_attn2 + (size_t)bh * NNv;
    const float* Bm = g_vh    + (size_t)bh * Nv * Dv;
    const int m0 = blockIdx.y * 64, n0 = blockIdx.x * 64;
    const int tid = threadIdx.x;
    const int tx = tid & 15, ty = tid >> 4;
    const int lr = tid >> 2, lq = tid & 3;   // for A tile
    const int kr = tid >> 4, nc4 = tid & 15; // for B tile

    float acc[4][4];
    #pragma unroll
    for (int i = 0; i < 4; i++)
        #pragma unroll
        for (int j = 0; j < 4; j++) acc[i][j] = 0.f;

    for (int k0 = 0; k0 < Nv; k0 += 16) {
        float4 va = make_float4(0.f, 0.f, 0.f, 0.f);
        if (m0 + lr < Nv)
            va = *(const float4*)(A + (size_t)(m0 + lr) * Nv + k0 + lq * 4);
        As[lq * 4 + 0][lr] = va.x;
        As[lq * 4 + 1][lr] = va.y;
        As[lq * 4 + 2][lr] = va.z;
        As[lq * 4 + 3][lr] = va.w;

        float4 vb = make_float4(0.f, 0.f, 0.f, 0.f);
        if (n0 + nc4 * 4 < Dv)
            vb = *(const float4*)(Bm + (size_t)(k0 + kr) * Dv + n0 + nc4 * 4);
        Bs[kr][nc4 * 4 + 0] = vb.x;
        Bs[kr][nc4 * 4 + 1] = vb.y;
        Bs[kr][nc4 * 4 + 2] = vb.z;
        Bs[kr][nc4 * 4 + 3] = vb.w;
        __syncthreads();

        #pragma unroll
        for (int kk = 0; kk < 16; kk++) {
            const float4 a  = *(const float4*)(&As[kk][ty * 4]);
            const float4 bq = *(const float4*)(&Bs[kk][tx * 4]);
            acc[0][0] += a.x * bq.x; acc[0][1] += a.x * bq.y; acc[0][2] += a.x * bq.z; acc[0][3] += a.x * bq.w;
            acc[1][0] += a.y * bq.x; acc[1][1] += a.y * bq.y; acc[1][2] += a.y * bq.z; acc[1][3] += a.y * bq.w;
            acc[2][0] += a.z * bq.x; acc[2][1] += a.z * bq.y; acc[2][2] += a.z * bq.z; acc[2][3] += a.z * bq.w;
            acc[3][0] += a.w * bq.x; acc[3][1] += a.w * bq.y; acc[3][2] += a.w * bq.z; acc[3][3] += a.w * bq.w;
        }
        __syncthreads();
    }

    const float a_s = g_bn[o];
    const float c_s = g_bn[8 + o];
    #pragma unroll
    for (int i = 0; i < 4; i++) {
        const int row = m0 + ty * 4 + i;
        if (row < Nv) {
            #pragma unroll
            for (int j = 0; j < 4; j++) {
                const int col = n0 + tx * 4 + j;
                if (col < Dv) {
                    const float vv = a_s * acc[i][j] + c_s * g_colsum[bh * Dv + col];
                    g_xcat[(size_t)(b * Nv + row) * Cv + o * Dv + col] = vv;
                }
            }
        }
    }
}

// ---------------- launch ---------------------------------------------------
extern "C" void kernel_launch(void* const* d_in, const int* in_sizes, int n_in,
                              void* d_out, int out_size) {
    const float* q     = (const float*)d_in[0];
    const float* k     = (const float*)d_in[1];
    const float* v     = (const float*)d_in[2];
    const float* Wq    = (const float*)d_in[3];
    const float* Wk    = (const float*)d_in[4];
    const float* Wv    = (const float*)d_in[5];
    const float* Wre   = (const float*)d_in[6];
    const float* bre   = (const float*)d_in[7];
    const float* gamma = (const float*)d_in[8];
    const float* beta  = (const float*)d_in[9];
    const float* Wp    = (const float*)d_in[10];
    const float* bp    = (const float*)d_in[11];
    float* out = (float*)d_out;

    void *pqh, *pkh, *pattn, *pxcat;
    cudaGetSymbolAddress(&pqh,   g_qh);
    cudaGetSymbolAddress(&pkh,   g_kh);
    cudaGetSymbolAddress(&pattn, g_attn);
    cudaGetSymbolAddress(&pxcat, g_xcat);

    zero_stats_kernel<<<1, 32>>>();
    conv_qkv_kernel<<<dim3(Bv * Nv, 3), 256>>>(q, k, v, Wq, Wk, Wv);
    colsum_v_kernel<<<Bv * Hv, 384>>>();

    // S = scale * Qh Kh^T   (batched over B*H)
    gemm_tn_kernel<<<dim3(13, 13, Bv * Hv), 256>>>(
        (const float*)pqh, (const float*)pkh, (float*)pattn,
        Nv, Nv, Dv, Dv, Dv, Nv,
        (long)Nv * Dv, (long)Nv * Dv, (long)NNv,
        SCALEF, nullptr);

    softmax_kernel<<<Bv * Hv * Nv, 256>>>();
    mix_stats_kernel<<<BNNv / 256, 256>>>(Wre, bre);
    bn_finalize_kernel<<<1, 8>>>(Wre, bre, gamma, beta);
    gemm_av_kernel<<<dim3(2, 13, Bv * Hv), 256>>>();

    // out = xcat @ Wp^T + bp
    gemm_tn_kernel<<<dim3(12, 98, 1), 256>>>(
        (const float*)pxcat, Wp, out,
        Bv * Nv, Cv, Cv, Cv, Cv, Cv,
        0L, 0L, 0L,
        1.0f, bp);
}

// round 5
// speedup vs baseline: 1.0516x; 1.0516x over previous
#include <cuda_runtime.h>
#include <math.h>

// Problem constants
#define Bv   8
#define Nv   784
#define Cv   768
#define Hv   8
#define Dv   96
#define NNv  614656            // 784*784
#define BNNv 4917248           // B*N*N
#define BHND 4816896           // B*H*N*D = B*N*C
#define SCALEF 0.1020620726159657495f   // 96^-0.5
#define BN_EPS 1e-5

// ---------------- scratch (static device memory; no allocs allowed) -------
__device__ float  g_qh[BHND];
__device__ float  g_kh[BHND];
__device__ float  g_vh[BHND];
__device__ float  g_attn [39337984];   // (B,H,N,N)  S (logits)
__device__ float  g_attn2[39337984];   // (B,O,N,N)  mixed A
__device__ float  g_xcat[BHND];        // (B,N,C) pre-projection
__device__ float  g_colsum[Bv*Hv*Dv];  // sum_m v[b,h,m,d]
__device__ double g_stats[16];         // [0..7]=sum(A-mu), [8..15]=sum((A-mu)^2)
__device__ float  g_bn[16];            // [0..7]=a_o, [8..15]=c_o

// ---------------- zero stats ---------------------------------------------
__global__ void zero_stats_kernel() {
    int t = threadIdx.x;
    if (t < 16) g_stats[t] = 0.0;
}

// ---------------- per-token 3x3 conv QKV projection ----------------------
__global__ void __launch_bounds__(256) conv_qkv_kernel(
        const float* __restrict__ q,
        const float* __restrict__ k,
        const float* __restrict__ v,
        const float* __restrict__ Wq,
        const float* __restrict__ Wk,
        const float* __restrict__ Wv) {
    __shared__ float xs[768];
    __shared__ float ws[81];
    const int t     = blockIdx.x;          // token = b*N + n
    const int which = blockIdx.y;
    const float* in = (which == 0) ? q : (which == 1) ? k : v;
    const float* W  = (which == 0) ? Wq : (which == 1) ? Wk : Wv;
    float* out      = (which == 0) ? g_qh : (which == 1) ? g_kh : g_vh;
    const int tid = threadIdx.x;

    const float* xin = in + (size_t)t * 768;
    for (int i = tid; i < 768; i += 256) xs[i] = xin[i];
    if (tid < 81) ws[tid] = W[tid];
    __syncthreads();

    const int b = t / Nv, n = t % Nv;
    #pragma unroll
    for (int r = 0; r < 3; r++) {
        const int c   = tid + 256 * r;
        const int co  = c >> 8;
        const int rem = c & 255;
        const int i   = rem >> 4, j = rem & 15;
        float acc = 0.f;
        #pragma unroll
        for (int ci = 0; ci < 3; ci++) {
            #pragma unroll
            for (int di = 0; di < 3; di++) {
                const int ii = i + di - 1;
                if (ii < 0 || ii > 15) continue;
                #pragma unroll
                for (int dj = 0; dj < 3; dj++) {
                    const int jj = j + dj - 1;
                    if (jj < 0 || jj > 15) continue;
                    acc += xs[ci * 256 + ii * 16 + jj] * ws[co * 27 + ci * 9 + di * 3 + dj];
                }
            }
        }
        const int h = c / 96, d = c % 96;
        out[((size_t)(b * Hv + h) * Nv + n) * Dv + d] = acc;
    }
}

// ---------------- column sums of V ----------------------------------------
__global__ void __launch_bounds__(384) colsum_v_kernel() {
    __shared__ float part[4][96];
    const int bh   = blockIdx.x;
    const int d    = threadIdx.x % 96;
    const int slc  = threadIdx.x / 96;
    const float* vp = g_vh + (size_t)bh * Nv * Dv + d;
    float s = 0.f;
    for (int m = slc; m < Nv; m += 4) s += vp[(size_t)m * Dv];
    part[slc][d] = s;
    __syncthreads();
    if (slc == 0)
        g_colsum[bh * Dv + d] = part[0][d] + part[1][d] + part[2][d] + part[3][d];
}

// ---------------- GEMM: C = alpha*A*B^T (+bias), 64x64x8 tile, 8x8 frag ---
// 64 threads. A: MxK row-major, B: NxK row-major. K % 8 == 0.
__global__ void __launch_bounds__(64) gemm64_kernel(
        const float* __restrict__ A,
        const float* __restrict__ Bm,
        float* __restrict__ C,
        int M, int Nn, int K,
        int lda, int ldb, int ldc,
        long sA, long sB, long sC,
        float alpha, const float* __restrict__ bias) {
    __shared__ float As[8][68];
    __shared__ float Bs[8][68];
    const int z = blockIdx.z;
    A  += (size_t)z * sA;
    Bm += (size_t)z * sB;
    C  += (size_t)z * sC;
    const int m0 = blockIdx.y * 64, n0 = blockIdx.x * 64;
    const int t  = threadIdx.x;
    const int tx = t & 7, ty = t >> 3;

    float acc[8][8];
    #pragma unroll
    for (int i = 0; i < 8; i++)
        #pragma unroll
        for (int j = 0; j < 8; j++) acc[i][j] = 0.f;

    const int  ar = m0 + t;
    const int  br = n0 + t;
    const bool avl = (ar < M);
    const bool bvl = (br < Nn);
    const float* Ap = A  + (size_t)ar * lda;
    const float* Bp = Bm + (size_t)br * ldb;
    const float4 z4 = make_float4(0.f, 0.f, 0.f, 0.f);

    for (int k0 = 0; k0 < K; k0 += 8) {
        const float4 a0 = avl ? *(const float4*)(Ap + k0)     : z4;
        const float4 a1 = avl ? *(const float4*)(Ap + k0 + 4) : z4;
        As[0][t] = a0.x; As[1][t] = a0.y; As[2][t] = a0.z; As[3][t] = a0.w;
        As[4][t] = a1.x; As[5][t] = a1.y; As[6][t] = a1.z; As[7][t] = a1.w;

        const float4 b0 = bvl ? *(const float4*)(Bp + k0)     : z4;
        const float4 b1 = bvl ? *(const float4*)(Bp + k0 + 4) : z4;
        Bs[0][t] = b0.x; Bs[1][t] = b0.y; Bs[2][t] = b0.z; Bs[3][t] = b0.w;
        Bs[4][t] = b1.x; Bs[5][t] = b1.y; Bs[6][t] = b1.z; Bs[7][t] = b1.w;
        __syncthreads();

        #pragma unroll
        for (int kk = 0; kk < 8; kk++) {
            float a8[8], b8[8];
            const float4 xa0 = *(const float4*)(&As[kk][ty * 8]);
            const float4 xa1 = *(const float4*)(&As[kk][ty * 8 + 4]);
            const float4 xb0 = *(const float4*)(&Bs[kk][tx * 8]);
            const float4 xb1 = *(const float4*)(&Bs[kk][tx * 8 + 4]);
            a8[0]=xa0.x; a8[1]=xa0.y; a8[2]=xa0.z; a8[3]=xa0.w;
            a8[4]=xa1.x; a8[5]=xa1.y; a8[6]=xa1.z; a8[7]=xa1.w;
            b8[0]=xb0.x; b8[1]=xb0.y; b8[2]=xb0.z; b8[3]=xb0.w;
            b8[4]=xb1.x; b8[5]=xb1.y; b8[6]=xb1.z; b8[7]=xb1.w;
            #pragma unroll
            for (int i = 0; i < 8; i++)
                #pragma unroll
                for (int j = 0; j < 8; j++)
                    acc[i][j] += a8[i] * b8[j];
        }
        __syncthreads();
    }

    #pragma unroll
    for (int i = 0; i < 8; i++) {
        const int row = m0 + ty * 8 + i;
        if (row < M) {
            #pragma unroll
            for (int jv = 0; jv < 2; jv++) {
                const int col = n0 + tx * 8 + jv * 4;
                if (col < Nn) {   // N % 4 == 0 and col % 4 == 0 -> whole float4 valid
                    float4 vv;
                    vv.x = acc[i][jv*4+0] * alpha;
                    vv.y = acc[i][jv*4+1] * alpha;
                    vv.z = acc[i][jv*4+2] * alpha;
                    vv.w = acc[i][jv*4+3] * alpha;
                    if (bias) {
                        const float4 bb = *(const float4*)(bias + col);
                        vv.x += bb.x; vv.y += bb.y; vv.z += bb.z; vv.w += bb.w;
                    }
                    *(float4*)(C + (size_t)row * ldc + col) = vv;
                }
            }
        }
    }
}

// ---------------- fused softmax + cross-head mix + BN stats ---------------
// One block per (b, n). Warp w softmaxes head w's row in smem, then all
// threads mix 8 heads -> 8 outputs, write A, and accumulate centered stats.
__global__ void __launch_bounds__(256) softmax_mix_stats_kernel(
        const float* __restrict__ Wre,
        const float* __restrict__ bre) {
    __shared__ float sm[8][Nv];
    __shared__ float sW[64];
    __shared__ float sb[8];
    __shared__ float part[8][16];
    const int bn  = blockIdx.x;           // b*Nv + n
    const int b   = bn / Nv, n = bn % Nv;
    const int tid = threadIdx.x;
    const int w   = tid >> 5, lane = tid & 31;
    if (tid < 64) sW[tid] = Wre[tid];
    if (tid < 8)  sb[tid] = bre[tid];

    // warp-per-head softmax
    const float* src = g_attn + ((size_t)(b * 8 + w) * Nv + n) * Nv;
    float lmax = -1e30f;
    for (int i = lane; i < Nv; i += 32) {
        const float vv = src[i];
        sm[w][i] = vv;
        lmax = fmaxf(lmax, vv);
    }
    #pragma unroll
    for (int s = 16; s; s >>= 1) lmax = fmaxf(lmax, __shfl_xor_sync(0xffffffffu, lmax, s));
    float lsum = 0.f;
    for (int i = lane; i < Nv; i += 32) {
        const float e = __expf(sm[w][i] - lmax);
        sm[w][i] = e;
        lsum += e;
    }
    #pragma unroll
    for (int s = 16; s; s >>= 1) lsum += __shfl_xor_sync(0xffffffffu, lsum, s);
    const float inv = 1.f / lsum;
    for (int i = lane; i < Nv; i += 32) sm[w][i] *= inv;
    __syncthreads();

    // per-thread analytic means
    float mu[8];
    #pragma unroll
    for (int o = 0; o < 8; o++) {
        float s = 0.f;
        #pragma unroll
        for (int h = 0; h < 8; h++) s += sW[o * 8 + h];
        mu[o] = s * (1.0f / (float)Nv) + sb[o];
    }

    // mix + stats
    float* ob = g_attn2 + (size_t)b * Hv * NNv + (size_t)n * Nv;
    float sd[8], sq[8];
    #pragma unroll
    for (int o = 0; o < 8; o++) { sd[o] = 0.f; sq[o] = 0.f; }
    for (int m = tid; m < Nv; m += 256) {
        float pr[8];
        #pragma unroll
        for (int h = 0; h < 8; h++) pr[h] = sm[h][m];
        #pragma unroll
        for (int o = 0; o < 8; o++) {
            float a = sb[o];
            #pragma unroll
            for (int h = 0; h < 8; h++) a += sW[o * 8 + h] * pr[h];
            ob[(size_t)o * NNv + m] = a;
            const float dd = a - mu[o];
            sd[o] += dd;
            sq[o] += dd * dd;
        }
    }
    #pragma unroll
    for (int o = 0; o < 8; o++) {
        #pragma unroll
        for (int s = 16; s; s >>= 1) {
            sd[o] += __shfl_xor_sync(0xffffffffu, sd[o], s);
            sq[o] += __shfl_xor_sync(0xffffffffu, sq[o], s);
        }
    }
    if (lane == 0) {
        #pragma unroll
        for (int o = 0; o < 8; o++) {
            part[w][o]     = sd[o];
            part[w][8 + o] = sq[o];
        }
    }
    __syncthreads();
    if (tid < 16) {
        float s = 0.f;
        #pragma unroll
        for (int ww = 0; ww < 8; ww++) s += part[ww][tid];
        atomicAdd(&g_stats[tid], (double)s);
    }
}

// ---------------- finalize BN scalars -------------------------------------
__global__ void bn_finalize_kernel(const float* __restrict__ Wre,
                                   const float* __restrict__ bre,
                                   const float* __restrict__ gamma,
                                   const float* __restrict__ beta) {
    const int o = threadIdx.x;
    if (o >= 8) return;
    const double cnt = (double)BNNv;
    float s = 0.f;
    #pragma unroll
    for (int h = 0; h < 8; h++) s += Wre[o * 8 + h];
    const double mu   = (double)s / (double)Nv + (double)bre[o];
    const double sd   = g_stats[o];
    const double sq   = g_stats[8 + o];
    const double mean = mu + sd / cnt;
    const double var  = sq / cnt - (sd / cnt) * (sd / cnt);
    const float a = gamma[o] * (float)(1.0 / sqrt(var + (double)BN_EPS));
    const float c = beta[o] - a * (float)mean;
    g_bn[o]     = a;
    g_bn[8 + o] = c;
}

// ---------------- AV GEMM with BN-affine epilogue -------------------------
// Tile 64(M) x 96(N=D), BK=8, 128 threads, 4x12 frags.
// Y[n,d] = a_o * (A @ V)[n,d] + c_o * colsumV[d], scattered into xcat.
__global__ void __launch_bounds__(128) gemm_av_kernel() {
    __shared__ float As[8][68];
    __shared__ float Bs[8][100];
    const int bh = blockIdx.z;
    const int b = bh >> 3, o = bh & 7;
    const float* A  = g_attn2 + (size_t)bh * NNv;        // 784 x 784
    const float* Bm = g_vh    + (size_t)bh * Nv * Dv;    // 784 x 96
    const int m0  = blockIdx.y * 64;
    const int t   = threadIdx.x;
    const int tx  = t & 7, ty = t >> 3;                  // ty 0..15, tx 0..7

    float acc[4][12];
    #pragma unroll
    for (int i = 0; i < 4; i++)
        #pragma unroll
        for (int j = 0; j < 12; j++) acc[i][j] = 0.f;

    const int  arow = m0 + (t >> 1);
    const int  akq  = (t & 1) * 4;
    const bool avl  = (arow < Nv);
    const float4 z4 = make_float4(0.f, 0.f, 0.f, 0.f);

    for (int k0 = 0; k0 < Nv; k0 += 8) {
        const float4 a = avl ? *(const float4*)(A + (size_t)arow * Nv + k0 + akq) : z4;
        As[akq + 0][t >> 1] = a.x;
        As[akq + 1][t >> 1] = a.y;
        As[akq + 2][t >> 1] = a.z;
        As[akq + 3][t >> 1] = a.w;
        if (t < 96) {
            #pragma unroll
            for (int r = 0; r < 8; r++)
                Bs[r][t] = Bm[(size_t)(k0 + r) * Dv + t];
        }
        __syncthreads();

        #pragma unroll
        for (int kk = 0; kk < 8; kk++) {
            const float4 a4 = *(const float4*)(&As[kk][ty * 4]);
            const float4 b0 = *(const float4*)(&Bs[kk][tx * 12]);
            const float4 b1 = *(const float4*)(&Bs[kk][tx * 12 + 4]);
            const float4 b2 = *(const float4*)(&Bs[kk][tx * 12 + 8]);
            float aa[4] = {a4.x, a4.y, a4.z, a4.w};
            float bb[12] = {b0.x,b0.y,b0.z,b0.w, b1.x,b1.y,b1.z,b1.w, b2.x,b2.y,b2.z,b2.w};
            #pragma unroll
            for (int i = 0; i < 4; i++)
                #pragma unroll
                for (int j = 0; j < 12; j++)
                    acc[i][j] += aa[i] * bb[j];
        }
        __syncthreads();
    }

    const float a_s = g_bn[o];
    const float c_s = g_bn[8 + o];
    #pragma unroll
    for (int i = 0; i < 4; i++) {
        const int row = m0 + ty * 4 + i;
        if (row < Nv) {
            float* dst = g_xcat + (size_t)(b * Nv + row) * Cv + o * Dv;
            #pragma unroll
            for (int j3 = 0; j3 < 3; j3++) {
                const int col = tx * 12 + j3 * 4;
                float4 vv;
                vv.x = a_s * acc[i][j3*4+0] + c_s * g_colsum[bh * Dv + col + 0];
                vv.y = a_s * acc[i][j3*4+1] + c_s * g_colsum[bh * Dv + col + 1];
                vv.z = a_s * acc[i][j3*4+2] + c_s * g_colsum[bh * Dv + col + 2];
                vv.w = a_s * acc[i][j3*4+3] + c_s * g_colsum[bh * Dv + col + 3];
                *(float4*)(dst + col) = vv;
            }
        }
    }
}

// ---------------- launch ---------------------------------------------------
extern "C" void kernel_launch(void* const* d_in, const int* in_sizes, int n_in,
                              void* d_out, int out_size) {
    const float* q     = (const float*)d_in[0];
    const float* k     = (const float*)d_in[1];
    const float* v     = (const float*)d_in[2];
    const float* Wq    = (const float*)d_in[3];
    const float* Wk    = (const float*)d_in[4];
    const float* Wv    = (const float*)d_in[5];
    const float* Wre   = (const float*)d_in[6];
    const float* bre   = (const float*)d_in[7];
    const float* gamma = (const float*)d_in[8];
    const float* beta  = (const float*)d_in[9];
    const float* Wp    = (const float*)d_in[10];
    const float* bp    = (const float*)d_in[11];
    float* out = (float*)d_out;

    void *pqh, *pkh, *pattn, *pxcat;
    cudaGetSymbolAddress(&pqh,   g_qh);
    cudaGetSymbolAddress(&pkh,   g_kh);
    cudaGetSymbolAddress(&pattn, g_attn);
    cudaGetSymbolAddress(&pxcat, g_xcat);

    zero_stats_kernel<<<1, 32>>>();
    conv_qkv_kernel<<<dim3(Bv * Nv, 3), 256>>>(q, k, v, Wq, Wk, Wv);
    colsum_v_kernel<<<Bv * Hv, 384>>>();

    // S = scale * Qh Kh^T   (batched over B*H)
    gemm64_kernel<<<dim3(13, 13, Bv * Hv), 64>>>(
        (const float*)pqh, (const float*)pkh, (float*)pattn,
        Nv, Nv, Dv, Dv, Dv, Nv,
        (long)Nv * Dv, (long)Nv * Dv, (long)NNv,
        SCALEF, nullptr);

    softmax_mix_stats_kernel<<<Bv * Nv, 256>>>(Wre, bre);
    bn_finalize_kernel<<<1, 8>>>(Wre, bre, gamma, beta);
    gemm_av_kernel<<<dim3(1, 13, Bv * Hv), 128>>>();

    // out = xcat @ Wp^T + bp
    gemm64_kernel<<<dim3(12, 98, 1), 64>>>(
        (const float*)pxcat, Wp, out,
        Bv * Nv, Cv, Cv, Cv, Cv, Cv,
        0L, 0L, 0L,
        1.0f, bp);
}

// round 9
// speedup vs baseline: 1.3804x; 1.3127x over previous
#include <cuda_runtime.h>
#include <cuda_bf16.h>
#include <math.h>
#include <stdint.h>

// Problem constants
#define Bv   8
#define Nv   784
#define Cv   768
#define Hv   8
#define Dv   96
#define NNv  614656            // 784*784
#define BNNv 4917248           // B*N*N
#define BHND 4816896           // B*H*N*D = B*N*C
#define SCALEF 0.1020620726159657495f   // 96^-0.5
#define BN_EPS 1e-5

// ---------------- scratch (static device memory; no allocs allowed) -------
__device__ float  g_qh[BHND];          // Q heads, pre-scaled by SCALEF
__device__ float  g_kh[BHND];
__device__ float  g_vh[BHND];          // (bh, m, d)
__device__ float  g_vt[BHND];          // (bh, d, m)  transposed V
__device__ float  g_attn [39337984];   // (B,H,N,N)  S (logits)
__device__ float  g_attn2[39337984];   // (B,O,N,N)  mixed A
__device__ float  g_xcat[BHND];        // (B,N,C) pre-projection
__device__ float  g_colsum[Bv*Hv*Dv];  // sum_m v[b,h,m,d]
__device__ double g_stats[16];         // [0..7]=sum(A-mu), [8..15]=sum((A-mu)^2)
__device__ float  g_bn[16];            // [0..7]=a_o, [8..15]=c_o

// ---------------- zero stats ---------------------------------------------
__global__ void zero_stats_kernel() {
    int t = threadIdx.x;
    if (t < 16) g_stats[t] = 0.0;
}

// ---------------- per-token 3x3 conv QKV projection ----------------------
__global__ void __launch_bounds__(256) conv_qkv_kernel(
        const float* __restrict__ q,
        const float* __restrict__ k,
        const float* __restrict__ v,
        const float* __restrict__ Wq,
        const float* __restrict__ Wk,
        const float* __restrict__ Wv) {
    __shared__ float xs[768];
    __shared__ float ws[81];
    const int t     = blockIdx.x;          // token = b*N + n
    const int which = blockIdx.y;
    const float* in = (which == 0) ? q : (which == 1) ? k : v;
    const float* W  = (which == 0) ? Wq : (which == 1) ? Wk : Wv;
    float* out      = (which == 0) ? g_qh : (which == 1) ? g_kh : g_vh;
    const float mul = (which == 0) ? SCALEF : 1.0f;   // fold attn scale into Q
    const int tid = threadIdx.x;

    const float* xin = in + (size_t)t * 768;
    for (int i = tid; i < 768; i += 256) xs[i] = xin[i];
    if (tid < 81) ws[tid] = W[tid];
    __syncthreads();

    const int b = t / Nv, n = t % Nv;
    #pragma unroll
    for (int r = 0; r < 3; r++) {
        const int c   = tid + 256 * r;
        const int co  = c >> 8;
        const int rem = c & 255;
        const int i   = rem >> 4, j = rem & 15;
        float acc = 0.f;
        #pragma unroll
        for (int ci = 0; ci < 3; ci++) {
            #pragma unroll
            for (int di = 0; di < 3; di++) {
                const int ii = i + di - 1;
                if (ii < 0 || ii > 15) continue;
                #pragma unroll
                for (int dj = 0; dj < 3; dj++) {
                    const int jj = j + dj - 1;
                    if (jj < 0 || jj > 15) continue;
                    acc += xs[ci * 256 + ii * 16 + jj] * ws[co * 27 + ci * 9 + di * 3 + dj];
                }
            }
        }
        const int h = c / 96, d = c % 96;
        out[((size_t)(b * Hv + h) * Nv + n) * Dv + d] = acc * mul;
    }
}

// ---------------- column sums of V ----------------------------------------
__global__ void __launch_bounds__(384) colsum_v_kernel() {
    __shared__ float part[4][96];
    const int bh   = blockIdx.x;
    const int d    = threadIdx.x % 96;
    const int slc  = threadIdx.x / 96;
    const float* vp = g_vh + (size_t)bh * Nv * Dv + d;
    float s = 0.f;
    for (int m = slc; m < Nv; m += 4) s += vp[(size_t)m * Dv];
    part[slc][d] = s;
    __syncthreads();
    if (slc == 0)
        g_colsum[bh * Dv + d] = part[0][d] + part[1][d] + part[2][d] + part[3][d];
}

// ---------------- transpose V: (bh, m, d) -> (bh, d, m) -------------------
// grid (25, 3, 64), block (32, 8)
__global__ void __launch_bounds__(256) transpose_v_kernel() {
    __shared__ float tile[32][33];
    const int bh = blockIdx.z;
    const int m0 = blockIdx.x * 32;
    const int d0 = blockIdx.y * 32;
    const float* src = g_vh + (size_t)bh * Nv * Dv;
    float* dst       = g_vt + (size_t)bh * Dv * Nv;
    const int tx = threadIdx.x, ty = threadIdx.y;
    #pragma unroll
    for (int i = 0; i < 32; i += 8) {
        const int m = m0 + ty + i;
        tile[ty + i][tx] = (m < Nv) ? src[(size_t)m * Dv + d0 + tx] : 0.f;
    }
    __syncthreads();
    #pragma unroll
    for (int i = 0; i < 32; i += 8) {
        const int d = d0 + ty + i;
        const int m = m0 + tx;
        if (m < Nv) dst[(size_t)d * Nv + m] = tile[tx][ty + i];
    }
}

// ---------------- bf16 split helpers --------------------------------------
__device__ __forceinline__ uint32_t pack2bf(float a, float b) {
    __nv_bfloat162 h = __floats2bfloat162_rn(a, b);
    return *(uint32_t*)&h;
}

__device__ __forceinline__ void mma_bf16(float* c, const uint32_t* a, const uint32_t* b) {
    asm volatile(
        "mma.sync.aligned.m16n8k16.row.col.f32.bf16.bf16.f32 "
        "{%0,%1,%2,%3}, {%4,%5,%6,%7}, {%8,%9}, {%0,%1,%2,%3};"
        : "+f"(c[0]), "+f"(c[1]), "+f"(c[2]), "+f"(c[3])
        : "r"(a[0]), "r"(a[1]), "r"(a[2]), "r"(a[3]), "r"(b[0]), "r"(b[1]));
}

// ---------------- shared body for bf16-split tensor-core GEMM -------------
// A: MxK row-major. B: NxK row-major. 64x64 block tile, BK=16, 4 warps.
// Each fp32 operand is split hi+lo (bf16); acc += hiA*hiB + hiA*loB + loA*hiB.
#define LDS2 20   // smem row stride in bf16 elements (40B)

struct MmaCtx {
    float acc[2][4][4];
    int m0, n0, wm, wn, g, t4;
};

__device__ __forceinline__ void mma_gemm_body(
        MmaCtx& cx,
        const float* __restrict__ A,
        const float* __restrict__ Bm,
        int M, int Nn, int K, int lda, int ldb,
        unsigned short (*AsH)[LDS2], unsigned short (*AsL)[LDS2],
        unsigned short (*BsH)[LDS2], unsigned short (*BsL)[LDS2]) {
    const int tid  = threadIdx.x;
    const int warp = tid >> 5, lane = tid & 31;
    cx.g  = lane >> 2;
    cx.t4 = lane & 3;
    cx.wm = (warp & 1) * 32;
    cx.wn = (warp >> 1) * 32;

    #pragma unroll
    for (int mf = 0; mf < 2; mf++)
        #pragma unroll
        for (int nf = 0; nf < 4; nf++)
            #pragma unroll
            for (int r = 0; r < 4; r++) cx.acc[mf][nf][r] = 0.f;

    const int lr = tid >> 1;          // 0..63
    const int hf = tid & 1;           // 0,1 -> k-offset 0 or 8
    const bool avld = (cx.m0 + lr) < M;
    const bool bvld = (cx.n0 + lr) < Nn;
    const float* Ap = A  + (size_t)(cx.m0 + lr) * lda + hf * 8;
    const float* Bp = Bm + (size_t)(cx.n0 + lr) * ldb + hf * 8;
    const float4 z4 = make_float4(0.f, 0.f, 0.f, 0.f);

    for (int k0 = 0; k0 < K; k0 += 16) {
        // ---- load + split into smem ----
        {
            const float4 x0 = avld ? *(const float4*)(Ap + k0)     : z4;
            const float4 x1 = avld ? *(const float4*)(Ap + k0 + 4) : z4;
            float xv[8] = {x0.x, x0.y, x0.z, x0.w, x1.x, x1.y, x1.z, x1.w};
            float hv[8], lv[8];
            #pragma unroll
            for (int i = 0; i < 8; i++) {
                hv[i] = __bfloat162float(__float2bfloat16_rn(xv[i]));
                lv[i] = xv[i] - hv[i];
            }
            uint32_t* dh = (uint32_t*)&AsH[lr][0] + hf * 4;
            uint32_t* dl = (uint32_t*)&AsL[lr][0] + hf * 4;
            #pragma unroll
            for (int i = 0; i < 4; i++) {
                dh[i] = pack2bf(hv[2*i], hv[2*i+1]);
                dl[i] = pack2bf(lv[2*i], lv[2*i+1]);
            }
        }
        {
            const float4 x0 = bvld ? *(const float4*)(Bp + k0)     : z4;
            const float4 x1 = bvld ? *(const float4*)(Bp + k0 + 4) : z4;
            float xv[8] = {x0.x, x0.y, x0.z, x0.w, x1.x, x1.y, x1.z, x1.w};
            float hv[8], lv[8];
            #pragma unroll
            for (int i = 0; i < 8; i++) {
                hv[i] = __bfloat162float(__float2bfloat16_rn(xv[i]));
                lv[i] = xv[i] - hv[i];
            }
            uint32_t* dh = (uint32_t*)&BsH[lr][0] + hf * 4;
            uint32_t* dl = (uint32_t*)&BsL[lr][0] + hf * 4;
            #pragma unroll
            for (int i = 0; i < 4; i++) {
                dh[i] = pack2bf(hv[2*i], hv[2*i+1]);
                dl[i] = pack2bf(lv[2*i], lv[2*i+1]);
            }
        }
        __syncthreads();

        // ---- fragment loads ----
        uint32_t aH[2][4], aL[2][4], bH[4][2], bL[4][2];
        #pragma unroll
        for (int mf = 0; mf < 2; mf++) {
            const int r0 = cx.wm + mf * 16 + cx.g;
            const uint32_t* h0 = (const uint32_t*)&AsH[r0][0];
            const uint32_t* h1 = (const uint32_t*)&AsH[r0 + 8][0];
            const uint32_t* l0 = (const uint32_t*)&AsL[r0][0];
            const uint32_t* l1 = (const uint32_t*)&AsL[r0 + 8][0];
            aH[mf][0] = h0[cx.t4];     aH[mf][1] = h1[cx.t4];
            aH[mf][2] = h0[cx.t4 + 4]; aH[mf][3] = h1[cx.t4 + 4];
            aL[mf][0] = l0[cx.t4];     aL[mf][1] = l1[cx.t4];
            aL[mf][2] = l0[cx.t4 + 4]; aL[mf][3] = l1[cx.t4 + 4];
        }
        #pragma unroll
        for (int nf = 0; nf < 4; nf++) {
            const int rb = cx.wn + nf * 8 + cx.g;
            const uint32_t* h = (const uint32_t*)&BsH[rb][0];
            const uint32_t* l = (const uint32_t*)&BsL[rb][0];
            bH[nf][0] = h[cx.t4]; bH[nf][1] = h[cx.t4 + 4];
            bL[nf][0] = l[cx.t4]; bL[nf][1] = l[cx.t4 + 4];
        }
        __syncthreads();

        // ---- mma: hi*hi + hi*lo + lo*hi ----
        #pragma unroll
        for (int mf = 0; mf < 2; mf++)
            #pragma unroll
            for (int nf = 0; nf < 4; nf++)
                mma_bf16(cx.acc[mf][nf], aH[mf], bH[nf]);
        #pragma unroll
        for (int mf = 0; mf < 2; mf++)
            #pragma unroll
            for (int nf = 0; nf < 4; nf++)
                mma_bf16(cx.acc[mf][nf], aH[mf], bL[nf]);
        #pragma unroll
        for (int mf = 0; mf < 2; mf++)
            #pragma unroll
            for (int nf = 0; nf < 4; nf++)
                mma_bf16(cx.acc[mf][nf], aL[mf], bH[nf]);
    }
}

// ---------------- plain GEMM kernel (MODE 0) ------------------------------
__global__ void __launch_bounds__(128) mma_gemm_plain_kernel(
        const float* __restrict__ A,
        const float* __restrict__ Bm,
        float* __restrict__ C,
        int M, int Nn, int K,
        int lda, int ldb, int ldc,
        long sA, long sB, long sC,
        const float* __restrict__ bias) {
    __shared__ __align__(16) unsigned short AsH[64][LDS2];
    __shared__ __align__(16) unsigned short AsL[64][LDS2];
    __shared__ __align__(16) unsigned short BsH[64][LDS2];
    __shared__ __align__(16) unsigned short BsL[64][LDS2];

    const int z = blockIdx.z;
    A  += (size_t)z * sA;
    Bm += (size_t)z * sB;
    C  += (size_t)z * sC;

    MmaCtx cx;
    cx.m0 = blockIdx.y * 64;
    cx.n0 = blockIdx.x * 64;
    mma_gemm_body(cx, A, Bm, M, Nn, K, lda, ldb, AsH, AsL, BsH, BsL);

    #pragma unroll
    for (int mf = 0; mf < 2; mf++) {
        #pragma unroll
        for (int nf = 0; nf < 4; nf++) {
            const int col = cx.n0 + cx.wn + nf * 8 + 2 * cx.t4;
            if (col >= Nn) continue;
            float bx = 0.f, by = 0.f;
            if (bias) {
                const float2 bb = *(const float2*)(bias + col);
                bx = bb.x; by = bb.y;
            }
            const int r0 = cx.m0 + cx.wm + mf * 16 + cx.g;
            if (r0 < M) {
                float2 vv;
                vv.x = cx.acc[mf][nf][0] + bx;
                vv.y = cx.acc[mf][nf][1] + by;
                *(float2*)(C + (size_t)r0 * ldc + col) = vv;
            }
            const int r1 = r0 + 8;
            if (r1 < M) {
                float2 vv;
                vv.x = cx.acc[mf][nf][2] + bx;
                vv.y = cx.acc[mf][nf][3] + by;
                *(float2*)(C + (size_t)r1 * ldc + col) = vv;
            }
        }
    }
}

// ---------------- AV GEMM kernel (MODE 1: BN-affine + colsum + scatter) ---
__global__ void __launch_bounds__(128) mma_gemm_av_kernel() {
    __shared__ __align__(16) unsigned short AsH[64][LDS2];
    __shared__ __align__(16) unsigned short AsL[64][LDS2];
    __shared__ __align__(16) unsigned short BsH[64][LDS2];
    __shared__ __align__(16) unsigned short BsL[64][LDS2];

    const int z = blockIdx.z;                 // bh = b*8 + o
    const float* A  = g_attn2 + (size_t)z * NNv;   // 784 x 784
    const float* Bm = g_vt    + (size_t)z * Dv * Nv; // 96 x 784 (V^T)

    MmaCtx cx;
    cx.m0 = blockIdx.y * 64;
    cx.n0 = blockIdx.x * 64;
    mma_gemm_body(cx, A, Bm, Nv, Dv, Nv, Nv, Nv, AsH, AsL, BsH, BsL);

    const int b = z >> 3, o = z & 7;
    const float a_s = g_bn[o];
    const float c_s = g_bn[8 + o];
    float* xc = g_xcat + (size_t)b * Nv * Cv + o * Dv;
    #pragma unroll
    for (int mf = 0; mf < 2; mf++) {
        #pragma unroll
        for (int nf = 0; nf < 4; nf++) {
            const int col = cx.n0 + cx.wn + nf * 8 + 2 * cx.t4;
            if (col >= Dv) continue;
            const float cxs = c_s * g_colsum[z * Dv + col];
            const float cys = c_s * g_colsum[z * Dv + col + 1];
            const int r0 = cx.m0 + cx.wm + mf * 16 + cx.g;
            if (r0 < Nv) {
                float2 vv;
                vv.x = a_s * cx.acc[mf][nf][0] + cxs;
                vv.y = a_s * cx.acc[mf][nf][1] + cys;
                *(float2*)(xc + (size_t)r0 * Cv + col) = vv;
            }
            const int r1 = r0 + 8;
            if (r1 < Nv) {
                float2 vv;
                vv.x = a_s * cx.acc[mf][nf][2] + cxs;
                vv.y = a_s * cx.acc[mf][nf][3] + cys;
                *(float2*)(xc + (size_t)r1 * Cv + col) = vv;
            }
        }
    }
}

// ---------------- fused softmax + cross-head mix + BN stats ---------------
__global__ void __launch_bounds__(256) softmax_mix_stats_kernel(
        const float* __restrict__ Wre,
        const float* __restrict__ bre) {
    __shared__ float sm[8][Nv];
    __shared__ float sW[64];
    __shared__ float sb[8];
    __shared__ float part[8][16];
    const int bn  = blockIdx.x;           // b*Nv + n
    const int b   = bn / Nv, n = bn % Nv;
    const int tid = threadIdx.x;
    const int w   = tid >> 5, lane = tid & 31;
    if (tid < 64) sW[tid] = Wre[tid];
    if (tid < 8)  sb[tid] = bre[tid];

    // warp-per-head softmax
    const float* src = g_attn + ((size_t)(b * 8 + w) * Nv + n) * Nv;
    float lmax = -1e30f;
    for (int i = lane; i < Nv; i += 32) {
        const float vv = src[i];
        sm[w][i] = vv;
        lmax = fmaxf(lmax, vv);
    }
    #pragma unroll
    for (int s = 16; s; s >>= 1) lmax = fmaxf(lmax, __shfl_xor_sync(0xffffffffu, lmax, s));
    float lsum = 0.f;
    for (int i = lane; i < Nv; i += 32) {
        const float e = __expf(sm[w][i] - lmax);
        sm[w][i] = e;
        lsum += e;
    }
    #pragma unroll
    for (int s = 16; s; s >>= 1) lsum += __shfl_xor_sync(0xffffffffu, lsum, s);
    const float inv = 1.f / lsum;
    for (int i = lane; i < Nv; i += 32) sm[w][i] *= inv;
    __syncthreads();

    // per-thread analytic means
    float mu[8];
    #pragma unroll
    for (int o = 0; o < 8; o++) {
        float s = 0.f;
        #pragma unroll
        for (int h = 0; h < 8; h++) s += sW[o * 8 + h];
        mu[o] = s * (1.0f / (float)Nv) + sb[o];
    }

    // mix + stats
    float* ob = g_attn2 + (size_t)b * Hv * NNv + (size_t)n * Nv;
    float sd[8], sq[8];
    #pragma unroll
    for (int o = 0; o < 8; o++) { sd[o] = 0.f; sq[o] = 0.f; }
    for (int m = tid; m < Nv; m += 256) {
        float pr[8];
        #pragma unroll
        for (int h = 0; h < 8; h++) pr[h] = sm[h][m];
        #pragma unroll
        for (int o = 0; o < 8; o++) {
            float a = sb[o];
            #pragma unroll
            for (int h = 0; h < 8; h++) a += sW[o * 8 + h] * pr[h];
            ob[(size_t)o * NNv + m] = a;
            const float dd = a - mu[o];
            sd[o] += dd;
            sq[o] += dd * dd;
        }
    }
    #pragma unroll
    for (int o = 0; o < 8; o++) {
        #pragma unroll
        for (int s = 16; s; s >>= 1) {
            sd[o] += __shfl_xor_sync(0xffffffffu, sd[o], s);
            sq[o] += __shfl_xor_sync(0xffffffffu, sq[o], s);
        }
    }
    if (lane == 0) {
        #pragma unroll
        for (int o = 0; o < 8; o++) {
            part[w][o]     = sd[o];
            part[w][8 + o] = sq[o];
        }
    }
    __syncthreads();
    if (tid < 16) {
        float s = 0.f;
        #pragma unroll
        for (int ww = 0; ww < 8; ww++) s += part[ww][tid];
        atomicAdd(&g_stats[tid], (double)s);
    }
}

// ---------------- finalize BN scalars -------------------------------------
__global__ void bn_finalize_kernel(const float* __restrict__ Wre,
                                   const float* __restrict__ bre,
                                   const float* __restrict__ gamma,
                                   const float* __restrict__ beta) {
    const int o = threadIdx.x;
    if (o >= 8) return;
    const double cnt = (double)BNNv;
    float s = 0.f;
    #pragma unroll
    for (int h = 0; h < 8; h++) s += Wre[o * 8 + h];
    const double mu   = (double)s / (double)Nv + (double)bre[o];
    const double sd   = g_stats[o];
    const double sq   = g_stats[8 + o];
    const double mean = mu + sd / cnt;
    const double var  = sq / cnt - (sd / cnt) * (sd / cnt);
    const float a = gamma[o] * (float)(1.0 / sqrt(var + (double)BN_EPS));
    const float c = beta[o] - a * (float)mean;
    g_bn[o]     = a;
    g_bn[8 + o] = c;
}

// ---------------- launch ---------------------------------------------------
extern "C" void kernel_launch(void* const* d_in, const int* in_sizes, int n_in,
                              void* d_out, int out_size) {
    const float* q     = (const float*)d_in[0];
    const float* k     = (const float*)d_in[1];
    const float* v     = (const float*)d_in[2];
    const float* Wq    = (const float*)d_in[3];
    const float* Wk    = (const float*)d_in[4];
    const float* Wv    = (const float*)d_in[5];
    const float* Wre   = (const float*)d_in[6];
    const float* bre   = (const float*)d_in[7];
    const float* gamma = (const float*)d_in[8];
    const float* beta  = (const float*)d_in[9];
    const float* Wp    = (const float*)d_in[10];
    const float* bp    = (const float*)d_in[11];
    float* out = (float*)d_out;

    void *pqh, *pkh, *pattn, *pxcat;
    cudaGetSymbolAddress(&pqh,    g_qh);
    cudaGetSymbolAddress(&pkh,    g_kh);
    cudaGetSymbolAddress(&pattn,  g_attn);
    cudaGetSymbolAddress(&pxcat,  g_xcat);

    zero_stats_kernel<<<1, 32>>>();
    conv_qkv_kernel<<<dim3(Bv * Nv, 3), 256>>>(q, k, v, Wq, Wk, Wv);
    colsum_v_kernel<<<Bv * Hv, 384>>>();
    transpose_v_kernel<<<dim3(25, 3, 64), dim3(32, 8)>>>();

    // S = Qs Kh^T (scale folded into Q), batched over B*H
    mma_gemm_plain_kernel<<<dim3(13, 13, Bv * Hv), 128>>>(
        (const float*)pqh, (const float*)pkh, (float*)pattn,
        Nv, Nv, Dv, Dv, Dv, Nv,
        (long)Nv * Dv, (long)Nv * Dv, (long)NNv,
        nullptr);

    softmax_mix_stats_kernel<<<Bv * Nv, 256>>>(Wre, bre);
    bn_finalize_kernel<<<1, 8>>>(Wre, bre, gamma, beta);

    // AV: per (b,o): xcat <- a_o*(A @ V) + c_o*colsum ; B operand = V^T
    mma_gemm_av_kernel<<<dim3(2, 13, Bv * Hv), 128>>>();

    // out = xcat @ Wp^T + bp
    mma_gemm_plain_kernel<<<dim3(12, 98, 1), 128>>>(
        (const float*)pxcat, Wp, out,
        Bv * Nv, Cv, Cv, Cv, Cv, Cv,
        0L, 0L, 0L,
        bp);
}

// round 10
// speedup vs baseline: 1.6790x; 1.2163x over previous
#include <cuda_runtime.h>
#include <cuda_bf16.h>
#include <math.h>
#include <stdint.h>

// Problem constants
#define Bv   8
#define Nv   784
#define Cv   768
#define Hv   8
#define Dv   96
#define NNv  614656            // 784*784
#define BNNv 4917248           // B*N*N
#define BHND 4816896           // B*H*N*D = B*N*C
#define NN8  39337984          // B*H*N*N
#define WPN  589824            // 768*768
#define SCALEF 0.1020620726159657495f   // 96^-0.5
#define BN_EPS 1e-5

// ---------------- scratch (static device memory; no allocs allowed) -------
__device__ __align__(16) __nv_bfloat16 g_qhh[BHND], g_qhl[BHND];   // Q split (pre-scaled)
__device__ __align__(16) __nv_bfloat16 g_khh[BHND], g_khl[BHND];   // K split
__device__ float  g_vh[BHND];                                       // V fp32 (bh, m, d)
__device__ __align__(16) __nv_bfloat16 g_vth[BHND], g_vtl[BHND];   // V^T split (bh, d, m)
__device__ float  g_attn[NN8];                                      // logits (B,H,N,N)
__device__ __align__(16) __nv_bfloat16 g_a2h[NN8], g_a2l[NN8];     // mixed A split (B,O,N,N)
__device__ __align__(16) __nv_bfloat16 g_xch[BHND], g_xcl[BHND];   // xcat split (B,N,C)
__device__ __align__(16) __nv_bfloat16 g_wph[WPN], g_wpl[WPN];     // Wp split
__device__ float  g_colsum[Bv*Hv*Dv];
__device__ double g_stats[16];
__device__ float  g_bn[16];

// ---------------- zero stats ---------------------------------------------
__global__ void zero_stats_kernel() {
    int t = threadIdx.x;
    if (t < 16) g_stats[t] = 0.0;
}

// ---------------- split helpers ------------------------------------------
__device__ __forceinline__ void split1(float x, __nv_bfloat16& h, __nv_bfloat16& l) {
    h = __float2bfloat16_rn(x);
    l = __float2bfloat16_rn(x - __bfloat162float(h));
}
__device__ __forceinline__ void split2(float x, float y, uint32_t& hi, uint32_t& lo) {
    __nv_bfloat162 h2, l2;
    h2.x = __float2bfloat16_rn(x);
    h2.y = __float2bfloat16_rn(y);
    l2.x = __float2bfloat16_rn(x - __bfloat162float(h2.x));
    l2.y = __float2bfloat16_rn(y - __bfloat162float(h2.y));
    hi = *(uint32_t*)&h2;
    lo = *(uint32_t*)&l2;
}

// ---------------- per-token 3x3 conv QKV projection ----------------------
__global__ void __launch_bounds__(256) conv_qkv_kernel(
        const float* __restrict__ q,
        const float* __restrict__ k,
        const float* __restrict__ v,
        const float* __restrict__ Wq,
        const float* __restrict__ Wk,
        const float* __restrict__ Wv) {
    __shared__ float xs[768];
    __shared__ float ws[81];
    const int t     = blockIdx.x;          // token = b*N + n
    const int which = blockIdx.y;
    const float* in = (which == 0) ? q : (which == 1) ? k : v;
    const float* W  = (which == 0) ? Wq : (which == 1) ? Wk : Wv;
    const float mul = (which == 0) ? SCALEF : 1.0f;
    __nv_bfloat16* outh = (which == 0) ? g_qhh : g_khh;
    __nv_bfloat16* outl = (which == 0) ? g_qhl : g_khl;
    const int tid = threadIdx.x;

    const float* xin = in + (size_t)t * 768;
    for (int i = tid; i < 768; i += 256) xs[i] = xin[i];
    if (tid < 81) ws[tid] = W[tid];
    __syncthreads();

    const int b = t / Nv, n = t % Nv;
    #pragma unroll
    for (int r = 0; r < 3; r++) {
        const int c   = tid + 256 * r;
        const int co  = c >> 8;
        const int rem = c & 255;
        const int i   = rem >> 4, j = rem & 15;
        float acc = 0.f;
        #pragma unroll
        for (int ci = 0; ci < 3; ci++) {
            #pragma unroll
            for (int di = 0; di < 3; di++) {
                const int ii = i + di - 1;
                if (ii < 0 || ii > 15) continue;
                #pragma unroll
                for (int dj = 0; dj < 3; dj++) {
                    const int jj = j + dj - 1;
                    if (jj < 0 || jj > 15) continue;
                    acc += xs[ci * 256 + ii * 16 + jj] * ws[co * 27 + ci * 9 + di * 3 + dj];
                }
            }
        }
        const int h = c / 96, d = c % 96;
        const size_t idx = ((size_t)(b * Hv + h) * Nv + n) * Dv + d;
        if (which == 2) {
            g_vh[idx] = acc;
        } else {
            __nv_bfloat16 hh, ll;
            split1(acc * mul, hh, ll);
            outh[idx] = hh;
            outl[idx] = ll;
        }
    }
}

// ---------------- column sums of V ----------------------------------------
__global__ void __launch_bounds__(384) colsum_v_kernel() {
    __shared__ float part[4][96];
    const int bh   = blockIdx.x;
    const int d    = threadIdx.x % 96;
    const int slc  = threadIdx.x / 96;
    const float* vp = g_vh + (size_t)bh * Nv * Dv + d;
    float s = 0.f;
    for (int m = slc; m < Nv; m += 4) s += vp[(size_t)m * Dv];
    part[slc][d] = s;
    __syncthreads();
    if (slc == 0)
        g_colsum[bh * Dv + d] = part[0][d] + part[1][d] + part[2][d] + part[3][d];
}

// ---------------- transpose V + split: (bh,m,d) -> hi/lo (bh,d,m) ---------
__global__ void __launch_bounds__(256) transpose_v_kernel() {
    __shared__ float tile[32][33];
    const int bh = blockIdx.z;
    const int m0 = blockIdx.x * 32;
    const int d0 = blockIdx.y * 32;
    const float* src = g_vh + (size_t)bh * Nv * Dv;
    const size_t dbase = (size_t)bh * Dv * Nv;
    const int tx = threadIdx.x, ty = threadIdx.y;
    #pragma unroll
    for (int i = 0; i < 32; i += 8) {
        const int m = m0 + ty + i;
        tile[ty + i][tx] = (m < Nv) ? src[(size_t)m * Dv + d0 + tx] : 0.f;
    }
    __syncthreads();
    #pragma unroll
    for (int i = 0; i < 32; i += 8) {
        const int d = d0 + ty + i;
        const int m = m0 + tx;
        if (m < Nv) {
            __nv_bfloat16 hh, ll;
            split1(tile[tx][ty + i], hh, ll);
            g_vth[dbase + (size_t)d * Nv + m] = hh;
            g_vtl[dbase + (size_t)d * Nv + m] = ll;
        }
    }
}

// ---------------- split Wp into hi/lo -------------------------------------
__global__ void __launch_bounds__(256) split_wp_kernel(const float* __restrict__ Wp) {
    const int i = blockIdx.x * 256 + threadIdx.x;
    if (i < WPN) {
        __nv_bfloat16 hh, ll;
        split1(Wp[i], hh, ll);
        g_wph[i] = hh;
        g_wpl[i] = ll;
    }
}

// ---------------- cp.async helpers ----------------------------------------
__device__ __forceinline__ void cp16(void* dst, const void* src, int valid) {
    uint32_t s = (uint32_t)__cvta_generic_to_shared(dst);
    int sz = valid ? 16 : 0;
    asm volatile("cp.async.cg.shared.global [%0], [%1], 16, %2;\n"
                 :: "r"(s), "l"(src), "r"(sz));
}

__device__ __forceinline__ void mma_bf16(float* c, const uint32_t* a, const uint32_t* b) {
    asm volatile(
        "mma.sync.aligned.m16n8k16.row.col.f32.bf16.bf16.f32 "
        "{%0,%1,%2,%3}, {%4,%5,%6,%7}, {%8,%9}, {%0,%1,%2,%3};"
        : "+f"(c[0]), "+f"(c[1]), "+f"(c[2]), "+f"(c[3])
        : "r"(a[0]), "r"(a[1]), "r"(a[2]), "r"(a[3]), "r"(b[0]), "r"(b[1]));
}

// ---------------- pipelined bf16-split GEMM core --------------------------
// Pre-split operands: Ah/Al (MxK row-major), Bh/Bl (NnxK row-major).
// 64x64 tile, BK=16, 4 warps, double-buffered cp.async.
// acc += Ah*Bh + Ah*Bl + Al*Bh
#define LDSB 24   // smem row stride in bf16 (48B) — conflict-free for frag loads

__device__ __forceinline__ void mma_core(
        float acc[2][4][4],
        const __nv_bfloat16* __restrict__ Ah, const __nv_bfloat16* __restrict__ Al,
        const __nv_bfloat16* __restrict__ Bh, const __nv_bfloat16* __restrict__ Bl,
        int M, int Nn, int K, int lda, int ldb, int m0, int n0,
        __nv_bfloat16 (*sm)[4][64][LDSB],
        int wm, int wn, int g, int t4) {
    const int tid = threadIdx.x;
    const int lr = tid >> 1, hf = tid & 1;
    const int aval = (m0 + lr) < M;
    const int bval = (n0 + lr) < Nn;
    const int arow = aval ? (m0 + lr) : 0;
    const int brow = bval ? (n0 + lr) : 0;
    const __nv_bfloat16* pAh = Ah + (size_t)arow * lda + hf * 8;
    const __nv_bfloat16* pAl = Al + (size_t)arow * lda + hf * 8;
    const __nv_bfloat16* pBh = Bh + (size_t)brow * ldb + hf * 8;
    const __nv_bfloat16* pBl = Bl + (size_t)brow * ldb + hf * 8;

    // prologue: stage 0
    cp16(&sm[0][0][lr][hf * 8], pAh, aval);
    cp16(&sm[0][1][lr][hf * 8], pAl, aval);
    cp16(&sm[0][2][lr][hf * 8], pBh, bval);
    cp16(&sm[0][3][lr][hf * 8], pBl, bval);
    asm volatile("cp.async.commit_group;\n");

    const int nIter = K / 16;
    for (int it = 0; it < nIter; it++) {
        if (it + 1 < nIter) {
            const int st = (it + 1) & 1;
            const int k0 = (it + 1) * 16;
            cp16(&sm[st][0][lr][hf * 8], pAh + k0, aval);
            cp16(&sm[st][1][lr][hf * 8], pAl + k0, aval);
            cp16(&sm[st][2][lr][hf * 8], pBh + k0, bval);
            cp16(&sm[st][3][lr][hf * 8], pBl + k0, bval);
            asm volatile("cp.async.commit_group;\n");
            asm volatile("cp.async.wait_group 1;\n");
        } else {
            asm volatile("cp.async.wait_group 0;\n");
        }
        __syncthreads();

        const int st = it & 1;
        uint32_t aH[2][4], aL[2][4], bH[4][2], bL[4][2];
        #pragma unroll
        for (int mf = 0; mf < 2; mf++) {
            const int r0 = wm + mf * 16 + g;
            const uint32_t* h0 = (const uint32_t*)&sm[st][0][r0][0];
            const uint32_t* h1 = (const uint32_t*)&sm[st][0][r0 + 8][0];
            const uint32_t* l0 = (const uint32_t*)&sm[st][1][r0][0];
            const uint32_t* l1 = (const uint32_t*)&sm[st][1][r0 + 8][0];
            aH[mf][0] = h0[t4];     aH[mf][1] = h1[t4];
            aH[mf][2] = h0[t4 + 4]; aH[mf][3] = h1[t4 + 4];
            aL[mf][0] = l0[t4];     aL[mf][1] = l1[t4];
            aL[mf][2] = l0[t4 + 4]; aL[mf][3] = l1[t4 + 4];
        }
        #pragma unroll
        for (int nf = 0; nf < 4; nf++) {
            const int rb = wn + nf * 8 + g;
            const uint32_t* h = (const uint32_t*)&sm[st][2][rb][0];
            const uint32_t* l = (const uint32_t*)&sm[st][3][rb][0];
            bH[nf][0] = h[t4]; bH[nf][1] = h[t4 + 4];
            bL[nf][0] = l[t4]; bL[nf][1] = l[t4 + 4];
        }

        #pragma unroll
        for (int mf = 0; mf < 2; mf++)
            #pragma unroll
            for (int nf = 0; nf < 4; nf++)
                mma_bf16(acc[mf][nf], aH[mf], bH[nf]);
        #pragma unroll
        for (int mf = 0; mf < 2; mf++)
            #pragma unroll
            for (int nf = 0; nf < 4; nf++)
                mma_bf16(acc[mf][nf], aH[mf], bL[nf]);
        #pragma unroll
        for (int mf = 0; mf < 2; mf++)
            #pragma unroll
            for (int nf = 0; nf < 4; nf++)
                mma_bf16(acc[mf][nf], aL[mf], bH[nf]);
        __syncthreads();
    }
}

// ---------------- plain GEMM (fp32 out, optional bias) --------------------
__global__ void __launch_bounds__(128) mma2_plain_kernel(
        const __nv_bfloat16* __restrict__ Ah, const __nv_bfloat16* __restrict__ Al,
        const __nv_bfloat16* __restrict__ Bh, const __nv_bfloat16* __restrict__ Bl,
        float* __restrict__ C,
        int M, int Nn, int K, int lda, int ldb, int ldc,
        long sA, long sB, long sC, const float* __restrict__ bias) {
    __shared__ __align__(16) __nv_bfloat16 sm[2][4][64][LDSB];
    const int z = blockIdx.z;
    Ah += (size_t)z * sA; Al += (size_t)z * sA;
    Bh += (size_t)z * sB; Bl += (size_t)z * sB;
    C  += (size_t)z * sC;
    const int m0 = blockIdx.y * 64, n0 = blockIdx.x * 64;
    const int warp = threadIdx.x >> 5, lane = threadIdx.x & 31;
    const int g = lane >> 2, t4 = lane & 3;
    const int wm = (warp & 1) * 32, wn = (warp >> 1) * 32;

    float acc[2][4][4];
    #pragma unroll
    for (int mf = 0; mf < 2; mf++)
        #pragma unroll
        for (int nf = 0; nf < 4; nf++)
            #pragma unroll
            for (int r = 0; r < 4; r++) acc[mf][nf][r] = 0.f;

    mma_core(acc, Ah, Al, Bh, Bl, M, Nn, K, lda, ldb, m0, n0, sm, wm, wn, g, t4);

    #pragma unroll
    for (int mf = 0; mf < 2; mf++) {
        #pragma unroll
        for (int nf = 0; nf < 4; nf++) {
            const int col = n0 + wn + nf * 8 + 2 * t4;
            if (col >= Nn) continue;
            float bx = 0.f, by = 0.f;
            if (bias) {
                const float2 bb = *(const float2*)(bias + col);
                bx = bb.x; by = bb.y;
            }
            const int r0 = m0 + wm + mf * 16 + g;
            if (r0 < M) {
                float2 vv; vv.x = acc[mf][nf][0] + bx; vv.y = acc[mf][nf][1] + by;
                *(float2*)(C + (size_t)r0 * ldc + col) = vv;
            }
            const int r1 = r0 + 8;
            if (r1 < M) {
                float2 vv; vv.x = acc[mf][nf][2] + bx; vv.y = acc[mf][nf][3] + by;
                *(float2*)(C + (size_t)r1 * ldc + col) = vv;
            }
        }
    }
}

// ---------------- AV GEMM (BN-affine + colsum, split-write into xcat) -----
__global__ void __launch_bounds__(128) mma2_av_kernel() {
    __shared__ __align__(16) __nv_bfloat16 sm[2][4][64][LDSB];
    const int z = blockIdx.z;                    // bh = b*8 + o
    const __nv_bfloat16* Ah = g_a2h + (size_t)z * NNv;
    const __nv_bfloat16* Al = g_a2l + (size_t)z * NNv;
    const __nv_bfloat16* Bh = g_vth + (size_t)z * Dv * Nv;
    const __nv_bfloat16* Bl = g_vtl + (size_t)z * Dv * Nv;
    const int m0 = blockIdx.y * 64, n0 = blockIdx.x * 64;
    const int warp = threadIdx.x >> 5, lane = threadIdx.x & 31;
    const int g = lane >> 2, t4 = lane & 3;
    const int wm = (warp & 1) * 32, wn = (warp >> 1) * 32;

    float acc[2][4][4];
    #pragma unroll
    for (int mf = 0; mf < 2; mf++)
        #pragma unroll
        for (int nf = 0; nf < 4; nf++)
            #pragma unroll
            for (int r = 0; r < 4; r++) acc[mf][nf][r] = 0.f;

    mma_core(acc, Ah, Al, Bh, Bl, Nv, Dv, Nv, Nv, Nv, m0, n0, sm, wm, wn, g, t4);

    const int b = z >> 3, o = z & 7;
    const float a_s = g_bn[o];
    const float c_s = g_bn[8 + o];
    const size_t xbase = (size_t)b * Nv * Cv + o * Dv;
    #pragma unroll
    for (int mf = 0; mf < 2; mf++) {
        #pragma unroll
        for (int nf = 0; nf < 4; nf++) {
            const int col = n0 + wn + nf * 8 + 2 * t4;
            if (col >= Dv) continue;
            const float cxs = c_s * g_colsum[z * Dv + col];
            const float cys = c_s * g_colsum[z * Dv + col + 1];
            const int r0 = m0 + wm + mf * 16 + g;
            if (r0 < Nv) {
                uint32_t hi, lo;
                split2(a_s * acc[mf][nf][0] + cxs, a_s * acc[mf][nf][1] + cys, hi, lo);
                *(uint32_t*)(g_xch + xbase + (size_t)r0 * Cv + col) = hi;
                *(uint32_t*)(g_xcl + xbase + (size_t)r0 * Cv + col) = lo;
            }
            const int r1 = r0 + 8;
            if (r1 < Nv) {
                uint32_t hi, lo;
                split2(a_s * acc[mf][nf][2] + cxs, a_s * acc[mf][nf][3] + cys, hi, lo);
                *(uint32_t*)(g_xch + xbase + (size_t)r1 * Cv + col) = hi;
                *(uint32_t*)(g_xcl + xbase + (size_t)r1 * Cv + col) = lo;
            }
        }
    }
}

// ---------------- fused softmax + cross-head mix + BN stats ---------------
__global__ void __launch_bounds__(256) softmax_mix_stats_kernel(
        const float* __restrict__ Wre,
        const float* __restrict__ bre) {
    __shared__ float smx[8][Nv];
    __shared__ float sW[64];
    __shared__ float sb[8];
    __shared__ float part[8][16];
    const int bn  = blockIdx.x;           // b*Nv + n
    const int b   = bn / Nv, n = bn % Nv;
    const int tid = threadIdx.x;
    const int w   = tid >> 5, lane = tid & 31;
    if (tid < 64) sW[tid] = Wre[tid];
    if (tid < 8)  sb[tid] = bre[tid];

    // warp-per-head softmax
    const float* src = g_attn + ((size_t)(b * 8 + w) * Nv + n) * Nv;
    float lmax = -1e30f;
    for (int i = lane; i < Nv; i += 32) {
        const float vv = src[i];
        smx[w][i] = vv;
        lmax = fmaxf(lmax, vv);
    }
    #pragma unroll
    for (int s = 16; s; s >>= 1) lmax = fmaxf(lmax, __shfl_xor_sync(0xffffffffu, lmax, s));
    float lsum = 0.f;
    for (int i = lane; i < Nv; i += 32) {
        const float e = __expf(smx[w][i] - lmax);
        smx[w][i] = e;
        lsum += e;
    }
    #pragma unroll
    for (int s = 16; s; s >>= 1) lsum += __shfl_xor_sync(0xffffffffu, lsum, s);
    const float inv = 1.f / lsum;
    for (int i = lane; i < Nv; i += 32) smx[w][i] *= inv;
    __syncthreads();

    // per-thread analytic means
    float mu[8];
    #pragma unroll
    for (int o = 0; o < 8; o++) {
        float s = 0.f;
        #pragma unroll
        for (int h = 0; h < 8; h++) s += sW[o * 8 + h];
        mu[o] = s * (1.0f / (float)Nv) + sb[o];
    }

    // mix + stats + split-write
    const size_t obase = (size_t)b * Hv * NNv + (size_t)n * Nv;
    float sd[8], sq[8];
    #pragma unroll
    for (int o = 0; o < 8; o++) { sd[o] = 0.f; sq[o] = 0.f; }
    for (int m = tid; m < Nv; m += 256) {
        float pr[8];
        #pragma unroll
        for (int h = 0; h < 8; h++) pr[h] = smx[h][m];
        #pragma unroll
        for (int o = 0; o < 8; o++) {
            float a = sb[o];
            #pragma unroll
            for (int h = 0; h < 8; h++) a += sW[o * 8 + h] * pr[h];
            __nv_bfloat16 hh, ll;
            split1(a, hh, ll);
            g_a2h[obase + (size_t)o * NNv + m] = hh;
            g_a2l[obase + (size_t)o * NNv + m] = ll;
            const float dd = a - mu[o];
            sd[o] += dd;
            sq[o] += dd * dd;
        }
    }
    #pragma unroll
    for (int o = 0; o < 8; o++) {
        #pragma unroll
        for (int s = 16; s; s >>= 1) {
            sd[o] += __shfl_xor_sync(0xffffffffu, sd[o], s);
            sq[o] += __shfl_xor_sync(0xffffffffu, sq[o], s);
        }
    }
    if (lane == 0) {
        #pragma unroll
        for (int o = 0; o < 8; o++) {
            part[w][o]     = sd[o];
            part[w][8 + o] = sq[o];
        }
    }
    __syncthreads();
    if (tid < 16) {
        float s = 0.f;
        #pragma unroll
        for (int ww = 0; ww < 8; ww++) s += part[ww][tid];
        atomicAdd(&g_stats[tid], (double)s);
    }
}

// ---------------- finalize BN scalars -------------------------------------
__global__ void bn_finalize_kernel(const float* __restrict__ Wre,
                                   const float* __restrict__ bre,
                                   const float* __restrict__ gamma,
                                   const float* __restrict__ beta) {
    const int o = threadIdx.x;
    if (o >= 8) return;
    const double cnt = (double)BNNv;
    float s = 0.f;
    #pragma unroll
    for (int h = 0; h < 8; h++) s += Wre[o * 8 + h];
    const double mu   = (double)s / (double)Nv + (double)bre[o];
    const double sd   = g_stats[o];
    const double sq   = g_stats[8 + o];
    const double mean = mu + sd / cnt;
    const double var  = sq / cnt - (sd / cnt) * (sd / cnt);
    const float a = gamma[o] * (float)(1.0 / sqrt(var + (double)BN_EPS));
    const float c = beta[o] - a * (float)mean;
    g_bn[o]     = a;
    g_bn[8 + o] = c;
}

// ---------------- launch ---------------------------------------------------
extern "C" void kernel_launch(void* const* d_in, const int* in_sizes, int n_in,
                              void* d_out, int out_size) {
    const float* q     = (const float*)d_in[0];
    const float* k     = (const float*)d_in[1];
    const float* v     = (const float*)d_in[2];
    const float* Wq    = (const float*)d_in[3];
    const float* Wk    = (const float*)d_in[4];
    const float* Wv    = (const float*)d_in[5];
    const float* Wre   = (const float*)d_in[6];
    const float* bre   = (const float*)d_in[7];
    const float* gamma = (const float*)d_in[8];
    const float* beta  = (const float*)d_in[9];
    const float* Wp    = (const float*)d_in[10];
    const float* bp    = (const float*)d_in[11];
    float* out = (float*)d_out;

    void *pqhh, *pqhl, *pkhh, *pkhl, *pattn, *pxch, *pxcl, *pwph, *pwpl;
    cudaGetSymbolAddress(&pqhh,  g_qhh);
    cudaGetSymbolAddress(&pqhl,  g_qhl);
    cudaGetSymbolAddress(&pkhh,  g_khh);
    cudaGetSymbolAddress(&pkhl,  g_khl);
    cudaGetSymbolAddress(&pattn, g_attn);
    cudaGetSymbolAddress(&pxch,  g_xch);
    cudaGetSymbolAddress(&pxcl,  g_xcl);
    cudaGetSymbolAddress(&pwph,  g_wph);
    cudaGetSymbolAddress(&pwpl,  g_wpl);

    zero_stats_kernel<<<1, 32>>>();
    conv_qkv_kernel<<<dim3(Bv * Nv, 3), 256>>>(q, k, v, Wq, Wk, Wv);
    colsum_v_kernel<<<Bv * Hv, 384>>>();
    transpose_v_kernel<<<dim3(25, 3, 64), dim3(32, 8)>>>();
    split_wp_kernel<<<(WPN + 255) / 256, 256>>>(Wp);

    // S = Qs Kh^T (scale folded into Q), batched over B*H
    mma2_plain_kernel<<<dim3(13, 13, Bv * Hv), 128>>>(
        (const __nv_bfloat16*)pqhh, (const __nv_bfloat16*)pqhl,
        (const __nv_bfloat16*)pkhh, (const __nv_bfloat16*)pkhl,
        (float*)pattn,
        Nv, Nv, Dv, Dv, Dv, Nv,
        (long)Nv * Dv, (long)Nv * Dv, (long)NNv,
        nullptr);

    softmax_mix_stats_kernel<<<Bv * Nv, 256>>>(Wre, bre);
    bn_finalize_kernel<<<1, 8>>>(Wre, bre, gamma, beta);

    // AV: per (b,o): xcat <- a_o*(A @ V) + c_o*colsum (split-write)
    mma2_av_kernel<<<dim3(2, 13, Bv * Hv), 128>>>();

    // out = xcat @ Wp^T + bp
    mma2_plain_kernel<<<dim3(12, 98, 1), 128>>>(
        (const __nv_bfloat16*)pxch, (const __nv_bfloat16*)pxcl,
        (const __nv_bfloat16*)pwph, (const __nv_bfloat16*)pwpl,
        out,
        Bv * Nv, Cv, Cv, Cv, Cv, Cv,
        0L, 0L, 0L,
        bp);
}

// round 12
// speedup vs baseline: 1.7004x; 1.0128x over previous
#include <cuda_runtime.h>
#include <cuda_bf16.h>
#include <math.h>
#include <stdint.h>

// Problem constants
#define Bv   8
#define Nv   784
#define Cv   768
#define Hv   8
#define Dv   96
#define NNv  614656            // 784*784
#define BNNv 4917248           // B*N*N
#define BHND 4816896           // B*H*N*D = B*N*C
#define NN8  39337984          // B*H*N*N
#define WPN  589824            // 768*768
#define SCALEF 0.1020620726159657495f   // 96^-0.5
#define BN_EPS 1e-5

// ---------------- scratch (static device memory; no allocs allowed) -------
__device__ __align__(16) __nv_bfloat16 g_qhh[BHND], g_qhl[BHND];   // Q split (pre-scaled)
__device__ __align__(16) __nv_bfloat16 g_khh[BHND], g_khl[BHND];   // K split
__device__ float  g_vh[BHND];                                       // V fp32 (bh, m, d)
__device__ __align__(16) __nv_bfloat16 g_vth[BHND], g_vtl[BHND];   // V^T split (bh, d, m)
__device__ float  g_attn[NN8];                                      // logits (B,H,N,N)
__device__ __align__(16) __nv_bfloat16 g_a2h[NN8], g_a2l[NN8];     // mixed A split (B,O,N,N)
__device__ __align__(16) __nv_bfloat16 g_xch[BHND], g_xcl[BHND];   // xcat split (B,N,C)
__device__ __align__(16) __nv_bfloat16 g_wph[WPN], g_wpl[WPN];     // Wp split
__device__ float  g_colsum[Bv*Hv*Dv];
__device__ double g_stats[16];
__device__ float  g_bn[16];

// ---------------- zero stats ---------------------------------------------
__global__ void zero_stats_kernel() {
    int t = threadIdx.x;
    if (t < 16) g_stats[t] = 0.0;
}

// ---------------- split helpers ------------------------------------------
__device__ __forceinline__ void split1(float x, __nv_bfloat16& h, __nv_bfloat16& l) {
    h = __float2bfloat16_rn(x);
    l = __float2bfloat16_rn(x - __bfloat162float(h));
}
__device__ __forceinline__ void split2(float x, float y, uint32_t& hi, uint32_t& lo) {
    __nv_bfloat162 h2, l2;
    h2.x = __float2bfloat16_rn(x);
    h2.y = __float2bfloat16_rn(y);
    l2.x = __float2bfloat16_rn(x - __bfloat162float(h2.x));
    l2.y = __float2bfloat16_rn(y - __bfloat162float(h2.y));
    hi = *(uint32_t*)&h2;
    lo = *(uint32_t*)&l2;
}

// ---------------- per-token 3x3 conv QKV projection ----------------------
__global__ void __launch_bounds__(256) conv_qkv_kernel(
        const float* __restrict__ q,
        const float* __restrict__ k,
        const float* __restrict__ v,
        const float* __restrict__ Wq,
        const float* __restrict__ Wk,
        const float* __restrict__ Wv) {
    __shared__ float xs[768];
    __shared__ float ws[81];
    const int t     = blockIdx.x;          // token = b*N + n
    const int which = blockIdx.y;
    const float* in = (which == 0) ? q : (which == 1) ? k : v;
    const float* W  = (which == 0) ? Wq : (which == 1) ? Wk : Wv;
    const float mul = (which == 0) ? SCALEF : 1.0f;
    __nv_bfloat16* outh = (which == 0) ? g_qhh : g_khh;
    __nv_bfloat16* outl = (which == 0) ? g_qhl : g_khl;
    const int tid = threadIdx.x;

    const float* xin = in + (size_t)t * 768;
    for (int i = tid; i < 768; i += 256) xs[i] = xin[i];
    if (tid < 81) ws[tid] = W[tid];
    __syncthreads();

    const int b = t / Nv, n = t % Nv;
    #pragma unroll
    for (int r = 0; r < 3; r++) {
        const int c   = tid + 256 * r;
        const int co  = c >> 8;
        const int rem = c & 255;
        const int i   = rem >> 4, j = rem & 15;
        float acc = 0.f;
        #pragma unroll
        for (int ci = 0; ci < 3; ci++) {
            #pragma unroll
            for (int di = 0; di < 3; di++) {
                const int ii = i + di - 1;
                if (ii < 0 || ii > 15) continue;
                #pragma unroll
                for (int dj = 0; dj < 3; dj++) {
                    const int jj = j + dj - 1;
                    if (jj < 0 || jj > 15) continue;
                    acc += xs[ci * 256 + ii * 16 + jj] * ws[co * 27 + ci * 9 + di * 3 + dj];
                }
            }
        }
        const int h = c / 96, d = c % 96;
        const size_t idx = ((size_t)(b * Hv + h) * Nv + n) * Dv + d;
        if (which == 2) {
            g_vh[idx] = acc;
        } else {
            __nv_bfloat16 hh, ll;
            split1(acc * mul, hh, ll);
            outh[idx] = hh;
            outl[idx] = ll;
        }
    }
}

// ---------------- column sums of V ----------------------------------------
__global__ void __launch_bounds__(384) colsum_v_kernel() {
    __shared__ float part[4][96];
    const int bh   = blockIdx.x;
    const int d    = threadIdx.x % 96;
    const int slc  = threadIdx.x / 96;
    const float* vp = g_vh + (size_t)bh * Nv * Dv + d;
    float s = 0.f;
    for (int m = slc; m < Nv; m += 4) s += vp[(size_t)m * Dv];
    part[slc][d] = s;
    __syncthreads();
    if (slc == 0)
        g_colsum[bh * Dv + d] = part[0][d] + part[1][d] + part[2][d] + part[3][d];
}

// ---------------- transpose V + split: (bh,m,d) -> hi/lo (bh,d,m) ---------
__global__ void __launch_bounds__(256) transpose_v_kernel() {
    __shared__ float tile[32][33];
    const int bh = blockIdx.z;
    const int m0 = blockIdx.x * 32;
    const int d0 = blockIdx.y * 32;
    const float* src = g_vh + (size_t)bh * Nv * Dv;
    const size_t dbase = (size_t)bh * Dv * Nv;
    const int tx = threadIdx.x, ty = threadIdx.y;
    #pragma unroll
    for (int i = 0; i < 32; i += 8) {
        const int m = m0 + ty + i;
        tile[ty + i][tx] = (m < Nv) ? src[(size_t)m * Dv + d0 + tx] : 0.f;
    }
    __syncthreads();
    #pragma unroll
    for (int i = 0; i < 32; i += 8) {
        const int d = d0 + ty + i;
        const int m = m0 + tx;
        if (m < Nv) {
            __nv_bfloat16 hh, ll;
            split1(tile[tx][ty + i], hh, ll);
            g_vth[dbase + (size_t)d * Nv + m] = hh;
            g_vtl[dbase + (size_t)d * Nv + m] = ll;
        }
    }
}

// ---------------- split Wp into hi/lo -------------------------------------
__global__ void __launch_bounds__(256) split_wp_kernel(const float* __restrict__ Wp) {
    const int i = blockIdx.x * 256 + threadIdx.x;
    if (i < WPN) {
        __nv_bfloat16 hh, ll;
        split1(Wp[i], hh, ll);
        g_wph[i] = hh;
        g_wpl[i] = ll;
    }
}

// ---------------- cp.async helpers ----------------------------------------
__device__ __forceinline__ void cp16(void* dst, const void* src, int valid) {
    uint32_t s = (uint32_t)__cvta_generic_to_shared(dst);
    int sz = valid ? 16 : 0;
    asm volatile("cp.async.cg.shared.global [%0], [%1], 16, %2;\n"
                 :: "r"(s), "l"(src), "r"(sz));
}

__device__ __forceinline__ void mma_bf16(float* c, const uint32_t* a, const uint32_t* b) {
    asm volatile(
        "mma.sync.aligned.m16n8k16.row.col.f32.bf16.bf16.f32 "
        "{%0,%1,%2,%3}, {%4,%5,%6,%7}, {%8,%9}, {%0,%1,%2,%3};"
        : "+f"(c[0]), "+f"(c[1]), "+f"(c[2]), "+f"(c[3])
        : "r"(a[0]), "r"(a[1]), "r"(a[2]), "r"(a[3]), "r"(b[0]), "r"(b[1]));
}

// ---------------- pipelined bf16-split GEMM core --------------------------
// Pre-split operands: Ah/Al (MxK row-major), Bh/Bl (NnxK row-major).
// 64x64 tile, BK=16, 4 warps, 3-stage cp.async pipeline, 1 sync/iter.
// acc += Ah*Bh + Ah*Bl + Al*Bh
#define LDSB 24   // smem row stride in bf16 (48B) — conflict-free frag loads

__device__ __forceinline__ void mma_core(
        float acc[2][4][4],
        const __nv_bfloat16* __restrict__ Ah, const __nv_bfloat16* __restrict__ Al,
        const __nv_bfloat16* __restrict__ Bh, const __nv_bfloat16* __restrict__ Bl,
        int M, int Nn, int K, int lda, int ldb, int m0, int n0,
        __nv_bfloat16 (*sm)[4][64][LDSB],
        int wm, int wn, int g, int t4) {
    const int tid = threadIdx.x;
    const int lr = tid >> 1, hf = tid & 1;
    const int aval = (m0 + lr) < M;
    const int bval = (n0 + lr) < Nn;
    const int arow = aval ? (m0 + lr) : 0;
    const int brow = bval ? (n0 + lr) : 0;
    const __nv_bfloat16* pAh = Ah + (size_t)arow * lda + hf * 8;
    const __nv_bfloat16* pAl = Al + (size_t)arow * lda + hf * 8;
    const __nv_bfloat16* pBh = Bh + (size_t)brow * ldb + hf * 8;
    const __nv_bfloat16* pBl = Bl + (size_t)brow * ldb + hf * 8;
    const int nIter = K / 16;          // 6, 48, or 49 here — always >= 3

    // prologue: stages 0 and 1
    cp16(&sm[0][0][lr][hf * 8], pAh, aval);
    cp16(&sm[0][1][lr][hf * 8], pAl, aval);
    cp16(&sm[0][2][lr][hf * 8], pBh, bval);
    cp16(&sm[0][3][lr][hf * 8], pBl, bval);
    asm volatile("cp.async.commit_group;\n");
    cp16(&sm[1][0][lr][hf * 8], pAh + 16, aval);
    cp16(&sm[1][1][lr][hf * 8], pAl + 16, aval);
    cp16(&sm[1][2][lr][hf * 8], pBh + 16, bval);
    cp16(&sm[1][3][lr][hf * 8], pBl + 16, bval);
    asm volatile("cp.async.commit_group;\n");

    int st = 0, wst = 2;
    for (int it = 0; it < nIter; it++) {
        // wait for stage `it` (groups complete in order; keep newest pending)
        if (it + 1 < nIter) {
            asm volatile("cp.async.wait_group 1;\n");
        } else {
            asm volatile("cp.async.wait_group 0;\n");
        }
        __syncthreads();   // all threads' stage-`it` data visible; prior readers done

        // issue stage it+2 (overwrites stage read in iter it-1 — fenced by sync)
        if (it + 2 < nIter) {
            const int k0 = (it + 2) * 16;
            cp16(&sm[wst][0][lr][hf * 8], pAh + k0, aval);
            cp16(&sm[wst][1][lr][hf * 8], pAl + k0, aval);
            cp16(&sm[wst][2][lr][hf * 8], pBh + k0, bval);
            cp16(&sm[wst][3][lr][hf * 8], pBl + k0, bval);
            asm volatile("cp.async.commit_group;\n");
            wst = (wst == 2) ? 0 : wst + 1;
        }

        // fragment loads from stage `st`
        uint32_t aH[2][4], aL[2][4], bH[4][2], bL[4][2];
        #pragma unroll
        for (int mf = 0; mf < 2; mf++) {
            const int r0 = wm + mf * 16 + g;
            const uint32_t* h0 = (const uint32_t*)&sm[st][0][r0][0];
            const uint32_t* h1 = (const uint32_t*)&sm[st][0][r0 + 8][0];
            const uint32_t* l0 = (const uint32_t*)&sm[st][1][r0][0];
            const uint32_t* l1 = (const uint32_t*)&sm[st][1][r0 + 8][0];
            aH[mf][0] = h0[t4];     aH[mf][1] = h1[t4];
            aH[mf][2] = h0[t4 + 4]; aH[mf][3] = h1[t4 + 4];
            aL[mf][0] = l0[t4];     aL[mf][1] = l1[t4];
            aL[mf][2] = l0[t4 + 4]; aL[mf][3] = l1[t4 + 4];
        }
        #pragma unroll
        for (int nf = 0; nf < 4; nf++) {
            const int rb = wn + nf * 8 + g;
            const uint32_t* h = (const uint32_t*)&sm[st][2][rb][0];
            const uint32_t* l = (const uint32_t*)&sm[st][3][rb][0];
            bH[nf][0] = h[t4]; bH[nf][1] = h[t4 + 4];
            bL[nf][0] = l[t4]; bL[nf][1] = l[t4 + 4];
        }
        st = (st == 2) ? 0 : st + 1;

        #pragma unroll
        for (int mf = 0; mf < 2; mf++)
            #pragma unroll
            for (int nf = 0; nf < 4; nf++)
                mma_bf16(acc[mf][nf], aH[mf], bH[nf]);
        #pragma unroll
        for (int mf = 0; mf < 2; mf++)
            #pragma unroll
            for (int nf = 0; nf < 4; nf++)
                mma_bf16(acc[mf][nf], aH[mf], bL[nf]);
        #pragma unroll
        for (int mf = 0; mf < 2; mf++)
            #pragma unroll
            for (int nf = 0; nf < 4; nf++)
                mma_bf16(acc[mf][nf], aL[mf], bH[nf]);
    }
}

// ---------------- plain GEMM (fp32 out, optional bias) --------------------
__global__ void __launch_bounds__(128) mma2_plain_kernel(
        const __nv_bfloat16* __restrict__ Ah, const __nv_bfloat16* __restrict__ Al,
        const __nv_bfloat16* __restrict__ Bh, const __nv_bfloat16* __restrict__ Bl,
        float* __restrict__ C,
        int M, int Nn, int K, int lda, int ldb, int ldc,
        long sA, long sB, long sC, const float* __restrict__ bias) {
    __shared__ __align__(16) __nv_bfloat16 sm[3][4][64][LDSB];
    const int z = blockIdx.z;
    Ah += (size_t)z * sA; Al += (size_t)z * sA;
    Bh += (size_t)z * sB; Bl += (size_t)z * sB;
    C  += (size_t)z * sC;
    const int m0 = blockIdx.y * 64, n0 = blockIdx.x * 64;
    const int warp = threadIdx.x >> 5, lane = threadIdx.x & 31;
    const int g = lane >> 2, t4 = lane & 3;
    const int wm = (warp & 1) * 32, wn = (warp >> 1) * 32;

    float acc[2][4][4];
    #pragma unroll
    for (int mf = 0; mf < 2; mf++)
        #pragma unroll
        for (int nf = 0; nf < 4; nf++)
            #pragma unroll
            for (int r = 0; r < 4; r++) acc[mf][nf][r] = 0.f;

    mma_core(acc, Ah, Al, Bh, Bl, M, Nn, K, lda, ldb, m0, n0, sm, wm, wn, g, t4);

    #pragma unroll
    for (int mf = 0; mf < 2; mf++) {
        #pragma unroll
        for (int nf = 0; nf < 4; nf++) {
            const int col = n0 + wn + nf * 8 + 2 * t4;
            if (col >= Nn) continue;
            float bx = 0.f, by = 0.f;
            if (bias) {
                const float2 bb = *(const float2*)(bias + col);
                bx = bb.x; by = bb.y;
            }
            const int r0 = m0 + wm + mf * 16 + g;
            if (r0 < M) {
                float2 vv; vv.x = acc[mf][nf][0] + bx; vv.y = acc[mf][nf][1] + by;
                *(float2*)(C + (size_t)r0 * ldc + col) = vv;
            }
            const int r1 = r0 + 8;
            if (r1 < M) {
                float2 vv; vv.x = acc[mf][nf][2] + bx; vv.y = acc[mf][nf][3] + by;
                *(float2*)(C + (size_t)r1 * ldc + col) = vv;
            }
        }
    }
}

// ---------------- AV GEMM (BN-affine + colsum, split-write into xcat) -----
__global__ void __launch_bounds__(128) mma2_av_kernel() {
    __shared__ __align__(16) __nv_bfloat16 sm[3][4][64][LDSB];
    const int z = blockIdx.z;                    // bh = b*8 + o
    const __nv_bfloat16* Ah = g_a2h + (size_t)z * NNv;
    const __nv_bfloat16* Al = g_a2l + (size_t)z * NNv;
    const __nv_bfloat16* Bh = g_vth + (size_t)z * Dv * Nv;
    const __nv_bfloat16* Bl = g_vtl + (size_t)z * Dv * Nv;
    const int m0 = blockIdx.y * 64, n0 = blockIdx.x * 64;
    const int warp = threadIdx.x >> 5, lane = threadIdx.x & 31;
    const int g = lane >> 2, t4 = lane & 3;
    const int wm = (warp & 1) * 32, wn = (warp >> 1) * 32;

    float acc[2][4][4];
    #pragma unroll
    for (int mf = 0; mf < 2; mf++)
        #pragma unroll
        for (int nf = 0; nf < 4; nf++)
            #pragma unroll
            for (int r = 0; r < 4; r++) acc[mf][nf][r] = 0.f;

    mma_core(acc, Ah, Al, Bh, Bl, Nv, Dv, Nv, Nv, Nv, m0, n0, sm, wm, wn, g, t4);

    const int b = z >> 3, o = z & 7;
    const float a_s = g_bn[o];
    const float c_s = g_bn[8 + o];
    const size_t xbase = (size_t)b * Nv * Cv + o * Dv;
    #pragma unroll
    for (int mf = 0; mf < 2; mf++) {
        #pragma unroll
        for (int nf = 0; nf < 4; nf++) {
            const int col = n0 + wn + nf * 8 + 2 * t4;
            if (col >= Dv) continue;
            const float cxs = c_s * g_colsum[z * Dv + col];
            const float cys = c_s * g_colsum[z * Dv + col + 1];
            const int r0 = m0 + wm + mf * 16 + g;
            if (r0 < Nv) {
                uint32_t hi, lo;
                split2(a_s * acc[mf][nf][0] + cxs, a_s * acc[mf][nf][1] + cys, hi, lo);
                *(uint32_t*)(g_xch + xbase + (size_t)r0 * Cv + col) = hi;
                *(uint32_t*)(g_xcl + xbase + (size_t)r0 * Cv + col) = lo;
            }
            const int r1 = r0 + 8;
            if (r1 < Nv) {
                uint32_t hi, lo;
                split2(a_s * acc[mf][nf][2] + cxs, a_s * acc[mf][nf][3] + cys, hi, lo);
                *(uint32_t*)(g_xch + xbase + (size_t)r1 * Cv + col) = hi;
                *(uint32_t*)(g_xcl + xbase + (size_t)r1 * Cv + col) = lo;
            }
        }
    }
}

// ---------------- fused softmax + cross-head mix + BN stats ---------------
__global__ void __launch_bounds__(256) softmax_mix_stats_kernel(
        const float* __restrict__ Wre,
        const float* __restrict__ bre) {
    __shared__ float smx[8][Nv];
    __shared__ float sW[64];
    __shared__ float sb[8];
    __shared__ float part[8][16];
    const int bn  = blockIdx.x;           // b*Nv + n
    const int b   = bn / Nv, n = bn % Nv;
    const int tid = threadIdx.x;
    const int w   = tid >> 5, lane = tid & 31;
    if (tid < 64) sW[tid] = Wre[tid];
    if (tid < 8)  sb[tid] = bre[tid];

    // warp-per-head softmax
    const float* src = g_attn + ((size_t)(b * 8 + w) * Nv + n) * Nv;
    float lmax = -1e30f;
    for (int i = lane; i < Nv; i += 32) {
        const float vv = src[i];
        smx[w][i] = vv;
        lmax = fmaxf(lmax, vv);
    }
    #pragma unroll
    for (int s = 16; s; s >>= 1) lmax = fmaxf(lmax, __shfl_xor_sync(0xffffffffu, lmax, s));
    float lsum = 0.f;
    for (int i = lane; i < Nv; i += 32) {
        const float e = __expf(smx[w][i] - lmax);
        smx[w][i] = e;
        lsum += e;
    }
    #pragma unroll
    for (int s = 16; s; s >>= 1) lsum += __shfl_xor_sync(0xffffffffu, lsum, s);
    const float inv = 1.f / lsum;
    for (int i = lane; i < Nv; i += 32) smx[w][i] *= inv;
    __syncthreads();

    // per-thread analytic means
    float mu[8];
    #pragma unroll
    for (int o = 0; o < 8; o++) {
        float s = 0.f;
        #pragma unroll
        for (int h = 0; h < 8; h++) s += sW[o * 8 + h];
        mu[o] = s * (1.0f / (float)Nv) + sb[o];
    }

    // mix + stats + split-write
    const size_t obase = (size_t)b * Hv * NNv + (size_t)n * Nv;
    float sd[8], sq[8];
    #pragma unroll
    for (int o = 0; o < 8; o++) { sd[o] = 0.f; sq[o] = 0.f; }
    for (int m = tid; m < Nv; m += 256) {
        float pr[8];
        #pragma unroll
        for (int h = 0; h < 8; h++) pr[h] = smx[h][m];
        #pragma unroll
        for (int o = 0; o < 8; o++) {
            float a = sb[o];
            #pragma unroll
            for (int h = 0; h < 8; h++) a += sW[o * 8 + h] * pr[h];
            __nv_bfloat16 hh, ll;
            split1(a, hh, ll);
            g_a2h[obase + (size_t)o * NNv + m] = hh;
            g_a2l[obase + (size_t)o * NNv + m] = ll;
            const float dd = a - mu[o];
            sd[o] += dd;
            sq[o] += dd * dd;
        }
    }
    #pragma unroll
    for (int o = 0; o < 8; o++) {
        #pragma unroll
        for (int s = 16; s; s >>= 1) {
            sd[o] += __shfl_xor_sync(0xffffffffu, sd[o], s);
            sq[o] += __shfl_xor_sync(0xffffffffu, sq[o], s);
        }
    }
    if (lane == 0) {
        #pragma unroll
        for (int o = 0; o < 8; o++) {
            part[w][o]     = sd[o];
            part[w][8 + o] = sq[o];
        }
    }
    __syncthreads();
    if (tid < 16) {
        float s = 0.f;
        #pragma unroll
        for (int ww = 0; ww < 8; ww++) s += part[ww][tid];
        atomicAdd(&g_stats[tid], (double)s);
    }
}

// ---------------- finalize BN scalars -------------------------------------
__global__ void bn_finalize_kernel(const float* __restrict__ Wre,
                                   const float* __restrict__ bre,
                                   const float* __restrict__ gamma,
                                   const float* __restrict__ beta) {
    const int o = threadIdx.x;
    if (o >= 8) return;
    const double cnt = (double)BNNv;
    float s = 0.f;
    #pragma unroll
    for (int h = 0; h < 8; h++) s += Wre[o * 8 + h];
    const double mu   = (double)s / (double)Nv + (double)bre[o];
    const double sd   = g_stats[o];
    const double sq   = g_stats[8 + o];
    const double mean = mu + sd / cnt;
    const double var  = sq / cnt - (sd / cnt) * (sd / cnt);
    const float a = gamma[o] * (float)(1.0 / sqrt(var + (double)BN_EPS));
    const float c = beta[o] - a * (float)mean;
    g_bn[o]     = a;
    g_bn[8 + o] = c;
}

// ---------------- launch ---------------------------------------------------
extern "C" void kernel_launch(void* const* d_in, const int* in_sizes, int n_in,
                              void* d_out, int out_size) {
    const float* q     = (const float*)d_in[0];
    const float* k     = (const float*)d_in[1];
    const float* v     = (const float*)d_in[2];
    const float* Wq    = (const float*)d_in[3];
    const float* Wk    = (const float*)d_in[4];
    const float* Wv    = (const float*)d_in[5];
    const float* Wre   = (const float*)d_in[6];
    const float* bre   = (const float*)d_in[7];
    const float* gamma = (const float*)d_in[8];
    const float* beta  = (const float*)d_in[9];
    const float* Wp    = (const float*)d_in[10];
    const float* bp    = (const float*)d_in[11];
    float* out = (float*)d_out;

    void *pqhh, *pqhl, *pkhh, *pkhl, *pattn, *pxch, *pxcl, *pwph, *pwpl;
    cudaGetSymbolAddress(&pqhh,  g_qhh);
    cudaGetSymbolAddress(&pqhl,  g_qhl);
    cudaGetSymbolAddress(&pkhh,  g_khh);
    cudaGetSymbolAddress(&pkhl,  g_khl);
    cudaGetSymbolAddress(&pattn, g_attn);
    cudaGetSymbolAddress(&pxch,  g_xch);
    cudaGetSymbolAddress(&pxcl,  g_xcl);
    cudaGetSymbolAddress(&pwph,  g_wph);
    cudaGetSymbolAddress(&pwpl,  g_wpl);

    zero_stats_kernel<<<1, 32>>>();
    conv_qkv_kernel<<<dim3(Bv * Nv, 3), 256>>>(q, k, v, Wq, Wk, Wv);
    colsum_v_kernel<<<Bv * Hv, 384>>>();
    transpose_v_kernel<<<dim3(25, 3, 64), dim3(32, 8)>>>();
    split_wp_kernel<<<(WPN + 255) / 256, 256>>>(Wp);

    // S = Qs Kh^T (scale folded into Q), batched over B*H
    mma2_plain_kernel<<<dim3(13, 13, Bv * Hv), 128>>>(
        (const __nv_bfloat16*)pqhh, (const __nv_bfloat16*)pqhl,
        (const __nv_bfloat16*)pkhh, (const __nv_bfloat16*)pkhl,
        (float*)pattn,
        Nv, Nv, Dv, Dv, Dv, Nv,
        (long)Nv * Dv, (long)Nv * Dv, (long)NNv,
        nullptr);

    softmax_mix_stats_kernel<<<Bv * Nv, 256>>>(Wre, bre);
    bn_finalize_kernel<<<1, 8>>>(Wre, bre, gamma, beta);

    // AV: per (b,o): xcat <- a_o*(A @ V) + c_o*colsum (split-write)
    mma2_av_kernel<<<dim3(2, 13, Bv * Hv), 128>>>();

    // out = xcat @ Wp^T + bp
    mma2_plain_kernel<<<dim3(12, 98, 1), 128>>>(
        (const __nv_bfloat16*)pxch, (const __nv_bfloat16*)pxcl,
        (const __nv_bfloat16*)pwph, (const __nv_bfloat16*)pwpl,
        out,
        Bv * Nv, Cv, Cv, Cv, Cv, Cv,
        0L, 0L, 0L,
        bp);
}

// round 14
// speedup vs baseline: 1.7891x; 1.0522x over previous
#include <cuda_runtime.h>
#include <cuda_bf16.h>
#include <math.h>
#include <stdint.h>

// Problem constants
#define Bv   8
#define Nv   784
#define Cv   768
#define Hv   8
#define Dv   96
#define NNv  614656            // 784*784
#define BNNv 4917248           // B*N*N
#define BHND 4816896           // B*H*N*D = B*N*C
#define NN8  39337984          // B*H*N*N
#define WPN  589824            // 768*768
#define SCALEF 0.1020620726159657495f   // 96^-0.5
#define BN_EPS 1e-5

// ---------------- scratch (static device memory; no allocs allowed) -------
__device__ __align__(16) __nv_bfloat16 g_qhh[BHND], g_qhl[BHND];   // Q split (pre-scaled)
__device__ __align__(16) __nv_bfloat16 g_khh[BHND], g_khl[BHND];   // K split
__device__ float  g_vh[BHND];                                       // V fp32 (bh, m, d)
__device__ __align__(16) __nv_bfloat16 g_vth[BHND], g_vtl[BHND];   // V^T split (bh, d, m)
__device__ float  g_attn[NN8];                                      // logits (B,H,N,N)
__device__ __align__(16) __nv_bfloat16 g_a2h[NN8], g_a2l[NN8];     // mixed A split (B,O,N,N)
__device__ __align__(16) __nv_bfloat16 g_xch[BHND], g_xcl[BHND];   // xcat split (B,N,C)
__device__ __align__(16) __nv_bfloat16 g_wph[WPN], g_wpl[WPN];     // Wp split
__device__ float  g_colsum[Bv*Hv*Dv];
__device__ double g_stats[16];
__device__ float  g_bn[16];

// ---------------- zero stats ---------------------------------------------
__global__ void zero_stats_kernel() {
    int t = threadIdx.x;
    if (t < 16) g_stats[t] = 0.0;
}

// ---------------- split helpers ------------------------------------------
__device__ __forceinline__ void split1(float x, __nv_bfloat16& h, __nv_bfloat16& l) {
    h = __float2bfloat16_rn(x);
    l = __float2bfloat16_rn(x - __bfloat162float(h));
}
__device__ __forceinline__ void split2(float x, float y, uint32_t& hi, uint32_t& lo) {
    __nv_bfloat162 h2, l2;
    h2.x = __float2bfloat16_rn(x);
    h2.y = __float2bfloat16_rn(y);
    l2.x = __float2bfloat16_rn(x - __bfloat162float(h2.x));
    l2.y = __float2bfloat16_rn(y - __bfloat162float(h2.y));
    hi = *(uint32_t*)&h2;
    lo = *(uint32_t*)&l2;
}

// ---------------- per-token 3x3 conv QKV projection ----------------------
__global__ void __launch_bounds__(256) conv_qkv_kernel(
        const float* __restrict__ q,
        const float* __restrict__ k,
        const float* __restrict__ v,
        const float* __restrict__ Wq,
        const float* __restrict__ Wk,
        const float* __restrict__ Wv) {
    __shared__ float xs[768];
    __shared__ float ws[81];
    const int t     = blockIdx.x;          // token = b*N + n
    const int which = blockIdx.y;
    const float* in = (which == 0) ? q : (which == 1) ? k : v;
    const float* W  = (which == 0) ? Wq : (which == 1) ? Wk : Wv;
    const float mul = (which == 0) ? SCALEF : 1.0f;
    __nv_bfloat16* outh = (which == 0) ? g_qhh : g_khh;
    __nv_bfloat16* outl = (which == 0) ? g_qhl : g_khl;
    const int tid = threadIdx.x;

    const float* xin = in + (size_t)t * 768;
    for (int i = tid; i < 768; i += 256) xs[i] = xin[i];
    if (tid < 81) ws[tid] = W[tid];
    __syncthreads();

    const int b = t / Nv, n = t % Nv;
    #pragma unroll
    for (int r = 0; r < 3; r++) {
        const int c   = tid + 256 * r;
        const int co  = c >> 8;
        const int rem = c & 255;
        const int i   = rem >> 4, j = rem & 15;
        float acc = 0.f;
        #pragma unroll
        for (int ci = 0; ci < 3; ci++) {
            #pragma unroll
            for (int di = 0; di < 3; di++) {
                const int ii = i + di - 1;
                if (ii < 0 || ii > 15) continue;
                #pragma unroll
                for (int dj = 0; dj < 3; dj++) {
                    const int jj = j + dj - 1;
                    if (jj < 0 || jj > 15) continue;
                    acc += xs[ci * 256 + ii * 16 + jj] * ws[co * 27 + ci * 9 + di * 3 + dj];
                }
            }
        }
        const int h = c / 96, d = c % 96;
        const size_t idx = ((size_t)(b * Hv + h) * Nv + n) * Dv + d;
        if (which == 2) {
            g_vh[idx] = acc;
        } else {
            __nv_bfloat16 hh, ll;
            split1(acc * mul, hh, ll);
            outh[idx] = hh;
            outl[idx] = ll;
        }
    }
}

// ---------------- column sums of V ----------------------------------------
__global__ void __launch_bounds__(384) colsum_v_kernel() {
    __shared__ float part[4][96];
    const int bh   = blockIdx.x;
    const int d    = threadIdx.x % 96;
    const int slc  = threadIdx.x / 96;
    const float* vp = g_vh + (size_t)bh * Nv * Dv + d;
    float s = 0.f;
    for (int m = slc; m < Nv; m += 4) s += vp[(size_t)m * Dv];
    part[slc][d] = s;
    __syncthreads();
    if (slc == 0)
        g_colsum[bh * Dv + d] = part[0][d] + part[1][d] + part[2][d] + part[3][d];
}

// ---------------- transpose V + split: (bh,m,d) -> hi/lo (bh,d,m) ---------
__global__ void __launch_bounds__(256) transpose_v_kernel() {
    __shared__ float tile[32][33];
    const int bh = blockIdx.z;
    const int m0 = blockIdx.x * 32;
    const int d0 = blockIdx.y * 32;
    const float* src = g_vh + (size_t)bh * Nv * Dv;
    const size_t dbase = (size_t)bh * Dv * Nv;
    const int tx = threadIdx.x, ty = threadIdx.y;
    #pragma unroll
    for (int i = 0; i < 32; i += 8) {
        const int m = m0 + ty + i;
        tile[ty + i][tx] = (m < Nv) ? src[(size_t)m * Dv + d0 + tx] : 0.f;
    }
    __syncthreads();
    #pragma unroll
    for (int i = 0; i < 32; i += 8) {
        const int d = d0 + ty + i;
        const int m = m0 + tx;
        if (m < Nv) {
            __nv_bfloat16 hh, ll;
            split1(tile[tx][ty + i], hh, ll);
            g_vth[dbase + (size_t)d * Nv + m] = hh;
            g_vtl[dbase + (size_t)d * Nv + m] = ll;
        }
    }
}

// ---------------- split Wp into hi/lo -------------------------------------
__global__ void __launch_bounds__(256) split_wp_kernel(const float* __restrict__ Wp) {
    const int i = blockIdx.x * 256 + threadIdx.x;
    if (i < WPN) {
        __nv_bfloat16 hh, ll;
        split1(Wp[i], hh, ll);
        g_wph[i] = hh;
        g_wpl[i] = ll;
    }
}

// ---------------- cp.async helpers ----------------------------------------
__device__ __forceinline__ void cp16(void* dst, const void* src, int valid) {
    uint32_t s = (uint32_t)__cvta_generic_to_shared(dst);
    int sz = valid ? 16 : 0;
    asm volatile("cp.async.cg.shared.global [%0], [%1], 16, %2;\n"
                 :: "r"(s), "l"(src), "r"(sz));
}

__device__ __forceinline__ void mma_bf16(float* c, const uint32_t* a, const uint32_t* b) {
    asm volatile(
        "mma.sync.aligned.m16n8k16.row.col.f32.bf16.bf16.f32 "
        "{%0,%1,%2,%3}, {%4,%5,%6,%7}, {%8,%9}, {%0,%1,%2,%3};"
        : "+f"(c[0]), "+f"(c[1]), "+f"(c[2]), "+f"(c[3])
        : "r"(a[0]), "r"(a[1]), "r"(a[2]), "r"(a[3]), "r"(b[0]), "r"(b[1]));
}

// ---------------- pipelined bf16-split GEMM core (64x64 tile) -------------
// Pre-split operands: Ah/Al (MxK row-major), Bh/Bl (NnxK row-major).
// 64x64 tile, BK=16, 4 warps, 3-stage cp.async pipeline, 1 sync/iter.
// acc += Ah*Bh + Ah*Bl + Al*Bh
#define LDSB 24   // smem row stride in bf16 (48B) — conflict-free frag loads

__device__ __forceinline__ void mma_core(
        float acc[2][4][4],
        const __nv_bfloat16* __restrict__ Ah, const __nv_bfloat16* __restrict__ Al,
        const __nv_bfloat16* __restrict__ Bh, const __nv_bfloat16* __restrict__ Bl,
        int M, int Nn, int K, int lda, int ldb, int m0, int n0,
        __nv_bfloat16 (*sm)[4][64][LDSB],
        int wm, int wn, int g, int t4) {
    const int tid = threadIdx.x;
    const int lr = tid >> 1, hf = tid & 1;
    const int aval = (m0 + lr) < M;
    const int bval = (n0 + lr) < Nn;
    const int arow = aval ? (m0 + lr) : 0;
    const int brow = bval ? (n0 + lr) : 0;
    const __nv_bfloat16* pAh = Ah + (size_t)arow * lda + hf * 8;
    const __nv_bfloat16* pAl = Al + (size_t)arow * lda + hf * 8;
    const __nv_bfloat16* pBh = Bh + (size_t)brow * ldb + hf * 8;
    const __nv_bfloat16* pBl = Bl + (size_t)brow * ldb + hf * 8;
    const int nIter = K / 16;          // 6, 48, or 49 here — always >= 3

    // prologue: stages 0 and 1
    cp16(&sm[0][0][lr][hf * 8], pAh, aval);
    cp16(&sm[0][1][lr][hf * 8], pAl, aval);
    cp16(&sm[0][2][lr][hf * 8], pBh, bval);
    cp16(&sm[0][3][lr][hf * 8], pBl, bval);
    asm volatile("cp.async.commit_group;\n");
    cp16(&sm[1][0][lr][hf * 8], pAh + 16, aval);
    cp16(&sm[1][1][lr][hf * 8], pAl + 16, aval);
    cp16(&sm[1][2][lr][hf * 8], pBh + 16, bval);
    cp16(&sm[1][3][lr][hf * 8], pBl + 16, bval);
    asm volatile("cp.async.commit_group;\n");

    int st = 0, wst = 2;
    for (int it = 0; it < nIter; it++) {
        if (it + 1 < nIter) {
            asm volatile("cp.async.wait_group 1;\n");
        } else {
            asm volatile("cp.async.wait_group 0;\n");
        }
        __syncthreads();

        if (it + 2 < nIter) {
            const int k0 = (it + 2) * 16;
            cp16(&sm[wst][0][lr][hf * 8], pAh + k0, aval);
            cp16(&sm[wst][1][lr][hf * 8], pAl + k0, aval);
            cp16(&sm[wst][2][lr][hf * 8], pBh + k0, bval);
            cp16(&sm[wst][3][lr][hf * 8], pBl + k0, bval);
            asm volatile("cp.async.commit_group;\n");
            wst = (wst == 2) ? 0 : wst + 1;
        }

        uint32_t aH[2][4], aL[2][4], bH[4][2], bL[4][2];
        #pragma unroll
        for (int mf = 0; mf < 2; mf++) {
            const int r0 = wm + mf * 16 + g;
            const uint32_t* h0 = (const uint32_t*)&sm[st][0][r0][0];
            const uint32_t* h1 = (const uint32_t*)&sm[st][0][r0 + 8][0];
            const uint32_t* l0 = (const uint32_t*)&sm[st][1][r0][0];
            const uint32_t* l1 = (const uint32_t*)&sm[st][1][r0 + 8][0];
            aH[mf][0] = h0[t4];     aH[mf][1] = h1[t4];
            aH[mf][2] = h0[t4 + 4]; aH[mf][3] = h1[t4 + 4];
            aL[mf][0] = l0[t4];     aL[mf][1] = l1[t4];
            aL[mf][2] = l0[t4 + 4]; aL[mf][3] = l1[t4 + 4];
        }
        #pragma unroll
        for (int nf = 0; nf < 4; nf++) {
            const int rb = wn + nf * 8 + g;
            const uint32_t* h = (const uint32_t*)&sm[st][2][rb][0];
            const uint32_t* l = (const uint32_t*)&sm[st][3][rb][0];
            bH[nf][0] = h[t4]; bH[nf][1] = h[t4 + 4];
            bL[nf][0] = l[t4]; bL[nf][1] = l[t4 + 4];
        }
        st = (st == 2) ? 0 : st + 1;

        #pragma unroll
        for (int mf = 0; mf < 2; mf++)
            #pragma unroll
            for (int nf = 0; nf < 4; nf++)
                mma_bf16(acc[mf][nf], aH[mf], bH[nf]);
        #pragma unroll
        for (int mf = 0; mf < 2; mf++)
            #pragma unroll
            for (int nf = 0; nf < 4; nf++)
                mma_bf16(acc[mf][nf], aH[mf], bL[nf]);
        #pragma unroll
        for (int mf = 0; mf < 2; mf++)
            #pragma unroll
            for (int nf = 0; nf < 4; nf++)
                mma_bf16(acc[mf][nf], aL[mf], bH[nf]);
    }
}

// ---------------- plain GEMM (fp32 out, optional bias) --------------------
__global__ void __launch_bounds__(128) mma2_plain_kernel(
        const __nv_bfloat16* __restrict__ Ah, const __nv_bfloat16* __restrict__ Al,
        const __nv_bfloat16* __restrict__ Bh, const __nv_bfloat16* __restrict__ Bl,
        float* __restrict__ C,
        int M, int Nn, int K, int lda, int ldb, int ldc,
        long sA, long sB, long sC, const float* __restrict__ bias) {
    __shared__ __align__(16) __nv_bfloat16 sm[3][4][64][LDSB];
    const int z = blockIdx.z;
    Ah += (size_t)z * sA; Al += (size_t)z * sA;
    Bh += (size_t)z * sB; Bl += (size_t)z * sB;
    C  += (size_t)z * sC;
    const int m0 = blockIdx.y * 64, n0 = blockIdx.x * 64;
    const int warp = threadIdx.x >> 5, lane = threadIdx.x & 31;
    const int g = lane >> 2, t4 = lane & 3;
    const int wm = (warp & 1) * 32, wn = (warp >> 1) * 32;

    float acc[2][4][4];
    #pragma unroll
    for (int mf = 0; mf < 2; mf++)
        #pragma unroll
        for (int nf = 0; nf < 4; nf++)
            #pragma unroll
            for (int r = 0; r < 4; r++) acc[mf][nf][r] = 0.f;

    mma_core(acc, Ah, Al, Bh, Bl, M, Nn, K, lda, ldb, m0, n0, sm, wm, wn, g, t4);

    #pragma unroll
    for (int mf = 0; mf < 2; mf++) {
        #pragma unroll
        for (int nf = 0; nf < 4; nf++) {
            const int col = n0 + wn + nf * 8 + 2 * t4;
            if (col >= Nn) continue;
            float bx = 0.f, by = 0.f;
            if (bias) {
                const float2 bb = *(const float2*)(bias + col);
                bx = bb.x; by = bb.y;
            }
            const int r0 = m0 + wm + mf * 16 + g;
            if (r0 < M) {
                float2 vv; vv.x = acc[mf][nf][0] + bx; vv.y = acc[mf][nf][1] + by;
                *(float2*)(C + (size_t)r0 * ldc + col) = vv;
            }
            const int r1 = r0 + 8;
            if (r1 < M) {
                float2 vv; vv.x = acc[mf][nf][2] + bx; vv.y = acc[mf][nf][3] + by;
                *(float2*)(C + (size_t)r1 * ldc + col) = vv;
            }
        }
    }
}

// ---------------- AV GEMM, 64x96 tile, 192 threads (6 warps, 2m x 3n) -----
// C_tile = A(784x784) x V^T(96x784)^T with BN-affine + colsum epilogue.
// Full 96-wide N tile: no wasted MMAs, mixed-A read exactly once.
__global__ void __launch_bounds__(192) mma3_av_kernel() {
    __shared__ __align__(16) __nv_bfloat16 smA[3][2][64][LDSB];
    __shared__ __align__(16) __nv_bfloat16 smB[3][2][96][LDSB];
    const int z = blockIdx.z;                    // bh = b*8 + o
    const __nv_bfloat16* Ah = g_a2h + (size_t)z * NNv;
    const __nv_bfloat16* Al = g_a2l + (size_t)z * NNv;
    const __nv_bfloat16* Bh = g_vth + (size_t)z * Dv * Nv;
    const __nv_bfloat16* Bl = g_vtl + (size_t)z * Dv * Nv;
    const int m0 = blockIdx.y * 64;
    const int tid = threadIdx.x;
    const int warp = tid >> 5, lane = tid & 31;
    const int g = lane >> 2, t4 = lane & 3;
    const int wm = (warp & 1) * 32, wn = (warp >> 1) * 32;   // wn in {0,32,64}

    float acc[2][4][4];
    #pragma unroll
    for (int mf = 0; mf < 2; mf++)
        #pragma unroll
        for (int nf = 0; nf < 4; nf++)
            #pragma unroll
            for (int r = 0; r < 4; r++) acc[mf][nf][r] = 0.f;

    const int nIter = Nv / 16;    // 49

    // stage loader: 640 cp16 ops over 192 threads (idx < 640)
    //  [0,128)   Ah rows 0..63   [128,256) Al
    //  [256,448) Bh rows 0..95   [448,640) Bl
    auto load_stage = [&](int stg, int kc) {
        #pragma unroll
        for (int i = 0; i < 4; i++) {
            const int idx = i * 192 + tid;
            if (idx >= 640) break;
            if (idx < 256) {
                const int part = idx >> 7;            // 0 hi, 1 lo
                const int rem  = idx & 127;
                const int row  = rem >> 1, hf = rem & 1;
                const int grow = m0 + row;
                const int valid = grow < Nv;
                const __nv_bfloat16* src =
                    (part ? Al : Ah) + (size_t)(valid ? grow : 0) * Nv + kc + hf * 8;
                cp16(&smA[stg][part][row][hf * 8], src, valid);
            } else {
                const int j = idx - 256;
                const int part = j >= 192;            // 0 hi, 1 lo
                const int rem  = part ? (j - 192) : j;
                const int row  = rem >> 1, hf = rem & 1;   // row 0..95 always valid
                const __nv_bfloat16* src =
                    (part ? Bl : Bh) + (size_t)row * Nv + kc + hf * 8;
                cp16(&smB[stg][part][row][hf * 8], src, 1);
            }
        }
    };

    load_stage(0, 0);
    asm volatile("cp.async.commit_group;\n");
    load_stage(1, 16);
    asm volatile("cp.async.commit_group;\n");

    int st = 0, wst = 2;
    for (int it = 0; it < nIter; it++) {
        if (it + 1 < nIter) {
            asm volatile("cp.async.wait_group 1;\n");
        } else {
            asm volatile("cp.async.wait_group 0;\n");
        }
        __syncthreads();

        if (it + 2 < nIter) {
            load_stage(wst, (it + 2) * 16);
            asm volatile("cp.async.commit_group;\n");
            wst = (wst == 2) ? 0 : wst + 1;
        }

        uint32_t aH[2][4], aL[2][4], bH[4][2], bL[4][2];
        #pragma unroll
        for (int mf = 0; mf < 2; mf++) {
            const int r0 = wm + mf * 16 + g;
            const uint32_t* h0 = (const uint32_t*)&smA[st][0][r0][0];
            const uint32_t* h1 = (const uint32_t*)&smA[st][0][r0 + 8][0];
            const uint32_t* l0 = (const uint32_t*)&smA[st][1][r0][0];
            const uint32_t* l1 = (const uint32_t*)&smA[st][1][r0 + 8][0];
            aH[mf][0] = h0[t4];     aH[mf][1] = h1[t4];
            aH[mf][2] = h0[t4 + 4]; aH[mf][3] = h1[t4 + 4];
            aL[mf][0] = l0[t4];     aL[mf][1] = l1[t4];
            aL[mf][2] = l0[t4 + 4]; aL[mf][3] = l1[t4 + 4];
        }
        #pragma unroll
        for (int nf = 0; nf < 4; nf++) {
            const int rb = wn + nf * 8 + g;
            const uint32_t* h = (const uint32_t*)&smB[st][0][rb][0];
            const uint32_t* l = (const uint32_t*)&smB[st][1][rb][0];
            bH[nf][0] = h[t4]; bH[nf][1] = h[t4 + 4];
            bL[nf][0] = l[t4]; bL[nf][1] = l[t4 + 4];
        }
        st = (st == 2) ? 0 : st + 1;

        #pragma unroll
        for (int mf = 0; mf < 2; mf++)
            #pragma unroll
            for (int nf = 0; nf < 4; nf++)
                mma_bf16(acc[mf][nf], aH[mf], bH[nf]);
        #pragma unroll
        for (int mf = 0; mf < 2; mf++)
            #pragma unroll
            for (int nf = 0; nf < 4; nf++)
                mma_bf16(acc[mf][nf], aH[mf], bL[nf]);
        #pragma unroll
        for (int mf = 0; mf < 2; mf++)
            #pragma unroll
            for (int nf = 0; nf < 4; nf++)
                mma_bf16(acc[mf][nf], aL[mf], bH[nf]);
    }

    // epilogue: BN affine + colsum, split-write into xcat
    const int b = z >> 3, o = z & 7;
    const float a_s = g_bn[o];
    const float c_s = g_bn[8 + o];
    const size_t xbase = (size_t)b * Nv * Cv + o * Dv;
    #pragma unroll
    for (int mf = 0; mf < 2; mf++) {
        #pragma unroll
        for (int nf = 0; nf < 4; nf++) {
            const int col = wn + nf * 8 + 2 * t4;       // 0..94, always < 96
            const float cxs = c_s * g_colsum[z * Dv + col];
            const float cys = c_s * g_colsum[z * Dv + col + 1];
            const int r0 = m0 + wm + mf * 16 + g;
            if (r0 < Nv) {
                uint32_t hi, lo;
                split2(a_s * acc[mf][nf][0] + cxs, a_s * acc[mf][nf][1] + cys, hi, lo);
                *(uint32_t*)(g_xch + xbase + (size_t)r0 * Cv + col) = hi;
                *(uint32_t*)(g_xcl + xbase + (size_t)r0 * Cv + col) = lo;
            }
            const int r1 = r0 + 8;
            if (r1 < Nv) {
                uint32_t hi, lo;
                split2(a_s * acc[mf][nf][2] + cxs, a_s * acc[mf][nf][3] + cys, hi, lo);
                *(uint32_t*)(g_xch + xbase + (size_t)r1 * Cv + col) = hi;
                *(uint32_t*)(g_xcl + xbase + (size_t)r1 * Cv + col) = lo;
            }
        }
    }
}

// ---------------- fused softmax + cross-head mix + BN stats ---------------
__global__ void __launch_bounds__(256) softmax_mix_stats_kernel(
        const float* __restrict__ Wre,
        const float* __restrict__ bre) {
    __shared__ float smx[8][Nv];
    __shared__ float sW[64];
    __shared__ float sb[8];
    __shared__ float part[8][16];
    const int bn  = blockIdx.x;           // b*Nv + n
    const int b   = bn / Nv, n = bn % Nv;
    const int tid = threadIdx.x;
    const int w   = tid >> 5, lane = tid & 31;
    if (tid < 64) sW[tid] = Wre[tid];
    if (tid < 8)  sb[tid] = bre[tid];

    // warp-per-head softmax
    const float* src = g_attn + ((size_t)(b * 8 + w) * Nv + n) * Nv;
    float lmax = -1e30f;
    for (int i = lane; i < Nv; i += 32) {
        const float vv = src[i];
        smx[w][i] = vv;
        lmax = fmaxf(lmax, vv);
    }
    #pragma unroll
    for (int s = 16; s; s >>= 1) lmax = fmaxf(lmax, __shfl_xor_sync(0xffffffffu, lmax, s));
    float lsum = 0.f;
    for (int i = lane; i < Nv; i += 32) {
        const float e = __expf(smx[w][i] - lmax);
        smx[w][i] = e;
        lsum += e;
    }
    #pragma unroll
    for (int s = 16; s; s >>= 1) lsum += __shfl_xor_sync(0xffffffffu, lsum, s);
    const float inv = 1.f / lsum;
    for (int i = lane; i < Nv; i += 32) smx[w][i] *= inv;
    __syncthreads();

    // per-thread analytic means
    float mu[8];
    #pragma unroll
    for (int o = 0; o < 8; o++) {
        float s = 0.f;
        #pragma unroll
        for (int h = 0; h < 8; h++) s += sW[o * 8 + h];
        mu[o] = s * (1.0f / (float)Nv) + sb[o];
    }

    // mix + stats + split-write
    const size_t obase = (size_t)b * Hv * NNv + (size_t)n * Nv;
    float sd[8], sq[8];
    #pragma unroll
    for (int o = 0; o < 8; o++) { sd[o] = 0.f; sq[o] = 0.f; }
    for (int m = tid; m < Nv; m += 256) {
        float pr[8];
        #pragma unroll
        for (int h = 0; h < 8; h++) pr[h] = smx[h][m];
        #pragma unroll
        for (int o = 0; o < 8; o++) {
            float a = sb[o];
            #pragma unroll
            for (int h = 0; h < 8; h++) a += sW[o * 8 + h] * pr[h];
            __nv_bfloat16 hh, ll;
            split1(a, hh, ll);
            g_a2h[obase + (size_t)o * NNv + m] = hh;
            g_a2l[obase + (size_t)o * NNv + m] = ll;
            const float dd = a - mu[o];
            sd[o] += dd;
            sq[o] += dd * dd;
        }
    }
    #pragma unroll
    for (int o = 0; o < 8; o++) {
        #pragma unroll
        for (int s = 16; s; s >>= 1) {
            sd[o] += __shfl_xor_sync(0xffffffffu, sd[o], s);
            sq[o] += __shfl_xor_sync(0xffffffffu, sq[o], s);
        }
    }
    if (lane == 0) {
        #pragma unroll
        for (int o = 0; o < 8; o++) {
            part[w][o]     = sd[o];
            part[w][8 + o] = sq[o];
        }
    }
    __syncthreads();
    if (tid < 16) {
        float s = 0.f;
        #pragma unroll
        for (int ww = 0; ww < 8; ww++) s += part[ww][tid];
        atomicAdd(&g_stats[tid], (double)s);
    }
}

// ---------------- finalize BN scalars -------------------------------------
__global__ void bn_finalize_kernel(const float* __restrict__ Wre,
                                   const float* __restrict__ bre,
                                   const float* __restrict__ gamma,
                                   const float* __restrict__ beta) {
    const int o = threadIdx.x;
    if (o >= 8) return;
    const double cnt = (double)BNNv;
    float s = 0.f;
    #pragma unroll
    for (int h = 0; h < 8; h++) s += Wre[o * 8 + h];
    const double mu   = (double)s / (double)Nv + (double)bre[o];
    const double sd   = g_stats[o];
    const double sq   = g_stats[8 + o];
    const double mean = mu + sd / cnt;
    const double var  = sq / cnt - (sd / cnt) * (sd / cnt);
    const float a = gamma[o] * (float)(1.0 / sqrt(var + (double)BN_EPS));
    const float c = beta[o] - a * (float)mean;
    g_bn[o]     = a;
    g_bn[8 + o] = c;
}

// ---------------- launch ---------------------------------------------------
extern "C" void kernel_launch(void* const* d_in, const int* in_sizes, int n_in,
                              void* d_out, int out_size) {
    const float* q     = (const float*)d_in[0];
    const float* k     = (const float*)d_in[1];
    const float* v     = (const float*)d_in[2];
    const float* Wq    = (const float*)d_in[3];
    const float* Wk    = (const float*)d_in[4];
    const float* Wv    = (const float*)d_in[5];
    const float* Wre   = (const float*)d_in[6];
    const float* bre   = (const float*)d_in[7];
    const float* gamma = (const float*)d_in[8];
    const float* beta  = (const float*)d_in[9];
    const float* Wp    = (const float*)d_in[10];
    const float* bp    = (const float*)d_in[11];
    float* out = (float*)d_out;

    void *pqhh, *pqhl, *pkhh, *pkhl, *pattn, *pxch, *pxcl, *pwph, *pwpl;
    cudaGetSymbolAddress(&pqhh,  g_qhh);
    cudaGetSymbolAddress(&pqhl,  g_qhl);
    cudaGetSymbolAddress(&pkhh,  g_khh);
    cudaGetSymbolAddress(&pkhl,  g_khl);
    cudaGetSymbolAddress(&pattn, g_attn);
    cudaGetSymbolAddress(&pxch,  g_xch);
    cudaGetSymbolAddress(&pxcl,  g_xcl);
    cudaGetSymbolAddress(&pwph,  g_wph);
    cudaGetSymbolAddress(&pwpl,  g_wpl);

    zero_stats_kernel<<<1, 32>>>();
    conv_qkv_kernel<<<dim3(Bv * Nv, 3), 256>>>(q, k, v, Wq, Wk, Wv);
    colsum_v_kernel<<<Bv * Hv, 384>>>();
    transpose_v_kernel<<<dim3(25, 3, 64), dim3(32, 8)>>>();
    split_wp_kernel<<<(WPN + 255) / 256, 256>>>(Wp);

    // S = Qs Kh^T (scale folded into Q), batched over B*H
    mma2_plain_kernel<<<dim3(13, 13, Bv * Hv), 128>>>(
        (const __nv_bfloat16*)pqhh, (const __nv_bfloat16*)pqhl,
        (const __nv_bfloat16*)pkhh, (const __nv_bfloat16*)pkhl,
        (float*)pattn,
        Nv, Nv, Dv, Dv, Dv, Nv,
        (long)Nv * Dv, (long)Nv * Dv, (long)NNv,
        nullptr);

    softmax_mix_stats_kernel<<<Bv * Nv, 256>>>(Wre, bre);
    bn_finalize_kernel<<<1, 8>>>(Wre, bre, gamma, beta);

    // AV: per (b,o): xcat <- a_o*(A @ V) + c_o*colsum (96-wide tile, split-write)
    mma3_av_kernel<<<dim3(1, 13, Bv * Hv), 192>>>();

    // out = xcat @ Wp^T + bp
    mma2_plain_kernel<<<dim3(12, 98, 1), 128>>>(
        (const __nv_bfloat16*)pxch, (const __nv_bfloat16*)pxcl,
        (const __nv_bfloat16*)pwph, (const __nv_bfloat16*)pwpl,
        out,
        Bv * Nv, Cv, Cv, Cv, Cv, Cv,
        0L, 0L, 0L,
        bp);
}

// round 16
// speedup vs baseline: 1.8553x; 1.0370x over previous
#include <cuda_runtime.h>
#include <cuda_bf16.h>
#include <math.h>
#include <stdint.h>

// Problem constants
#define Bv   8
#define Nv   784
#define Cv   768
#define Hv   8
#define Dv   96
#define NNv  614656            // 784*784
#define BNNv 4917248           // B*N*N
#define BHND 4816896           // B*H*N*D = B*N*C
#define NN8  39337984          // B*H*N*N
#define WPN  589824            // 768*768
#define SCALEF 0.1020620726159657495f   // 96^-0.5
#define BN_EPS 1e-5

// ---------------- scratch (static device memory; no allocs allowed) -------
__device__ __align__(16) __nv_bfloat16 g_qhh[BHND], g_qhl[BHND];   // Q split (pre-scaled)
__device__ __align__(16) __nv_bfloat16 g_khh[BHND], g_khl[BHND];   // K split
__device__ float  g_vh[BHND];                                       // V fp32 (bh, m, d)
__device__ __align__(16) __nv_bfloat16 g_vth[BHND], g_vtl[BHND];   // V^T split (bh, d, m)
__device__ float  g_attn[NN8];                                      // logits (B,H,N,N)
__device__ __align__(16) __nv_bfloat16 g_a2h[NN8], g_a2l[NN8];     // mixed A split (B,O,N,N)
__device__ __align__(16) __nv_bfloat16 g_xch[BHND], g_xcl[BHND];   // xcat split (B,N,C)
__device__ __align__(16) __nv_bfloat16 g_wph[WPN], g_wpl[WPN];     // Wp split
__device__ float  g_colsum[Bv*Hv*Dv];
__device__ double g_stats[16];
__device__ float  g_bn[16];

// ---------------- zero stats ---------------------------------------------
__global__ void zero_stats_kernel() {
    int t = threadIdx.x;
    if (t < 16) g_stats[t] = 0.0;
}

// ---------------- split helpers ------------------------------------------
__device__ __forceinline__ void split1(float x, __nv_bfloat16& h, __nv_bfloat16& l) {
    h = __float2bfloat16_rn(x);
    l = __float2bfloat16_rn(x - __bfloat162float(h));
}
__device__ __forceinline__ void split2(float x, float y, uint32_t& hi, uint32_t& lo) {
    __nv_bfloat162 h2, l2;
    h2.x = __float2bfloat16_rn(x);
    h2.y = __float2bfloat16_rn(y);
    l2.x = __float2bfloat16_rn(x - __bfloat162float(h2.x));
    l2.y = __float2bfloat16_rn(y - __bfloat162float(h2.y));
    hi = *(uint32_t*)&h2;
    lo = *(uint32_t*)&l2;
}

// ---------------- per-token 3x3 conv QKV projection ----------------------
__global__ void __launch_bounds__(256) conv_qkv_kernel(
        const float* __restrict__ q,
        const float* __restrict__ k,
        const float* __restrict__ v,
        const float* __restrict__ Wq,
        const float* __restrict__ Wk,
        const float* __restrict__ Wv) {
    __shared__ float xs[768];
    __shared__ float ws[81];
    const int t     = blockIdx.x;          // token = b*N + n
    const int which = blockIdx.y;
    const float* in = (which == 0) ? q : (which == 1) ? k : v;
    const float* W  = (which == 0) ? Wq : (which == 1) ? Wk : Wv;
    const float mul = (which == 0) ? SCALEF : 1.0f;
    __nv_bfloat16* outh = (which == 0) ? g_qhh : g_khh;
    __nv_bfloat16* outl = (which == 0) ? g_qhl : g_khl;
    const int tid = threadIdx.x;

    const float* xin = in + (size_t)t * 768;
    for (int i = tid; i < 768; i += 256) xs[i] = xin[i];
    if (tid < 81) ws[tid] = W[tid];
    __syncthreads();

    const int b = t / Nv, n = t % Nv;
    #pragma unroll
    for (int r = 0; r < 3; r++) {
        const int c   = tid + 256 * r;
        const int co  = c >> 8;
        const int rem = c & 255;
        const int i   = rem >> 4, j = rem & 15;
        float acc = 0.f;
        #pragma unroll
        for (int ci = 0; ci < 3; ci++) {
            #pragma unroll
            for (int di = 0; di < 3; di++) {
                const int ii = i + di - 1;
                if (ii < 0 || ii > 15) continue;
                #pragma unroll
                for (int dj = 0; dj < 3; dj++) {
                    const int jj = j + dj - 1;
                    if (jj < 0 || jj > 15) continue;
                    acc += xs[ci * 256 + ii * 16 + jj] * ws[co * 27 + ci * 9 + di * 3 + dj];
                }
            }
        }
        const int h = c / 96, d = c % 96;
        const size_t idx = ((size_t)(b * Hv + h) * Nv + n) * Dv + d;
        if (which == 2) {
            g_vh[idx] = acc;
        } else {
            __nv_bfloat16 hh, ll;
            split1(acc * mul, hh, ll);
            outh[idx] = hh;
            outl[idx] = ll;
        }
    }
}

// ---------------- column sums of V ----------------------------------------
__global__ void __launch_bounds__(384) colsum_v_kernel() {
    __shared__ float part[4][96];
    const int bh   = blockIdx.x;
    const int d    = threadIdx.x % 96;
    const int slc  = threadIdx.x / 96;
    const float* vp = g_vh + (size_t)bh * Nv * Dv + d;
    float s = 0.f;
    for (int m = slc; m < Nv; m += 4) s += vp[(size_t)m * Dv];
    part[slc][d] = s;
    __syncthreads();
    if (slc == 0)
        g_colsum[bh * Dv + d] = part[0][d] + part[1][d] + part[2][d] + part[3][d];
}

// ---------------- transpose V + split: (bh,m,d) -> hi/lo (bh,d,m) ---------
__global__ void __launch_bounds__(256) transpose_v_kernel() {
    __shared__ float tile[32][33];
    const int bh = blockIdx.z;
    const int m0 = blockIdx.x * 32;
    const int d0 = blockIdx.y * 32;
    const float* src = g_vh + (size_t)bh * Nv * Dv;
    const size_t dbase = (size_t)bh * Dv * Nv;
    const int tx = threadIdx.x, ty = threadIdx.y;
    #pragma unroll
    for (int i = 0; i < 32; i += 8) {
        const int m = m0 + ty + i;
        tile[ty + i][tx] = (m < Nv) ? src[(size_t)m * Dv + d0 + tx] : 0.f;
    }
    __syncthreads();
    #pragma unroll
    for (int i = 0; i < 32; i += 8) {
        const int d = d0 + ty + i;
        const int m = m0 + tx;
        if (m < Nv) {
            __nv_bfloat16 hh, ll;
            split1(tile[tx][ty + i], hh, ll);
            g_vth[dbase + (size_t)d * Nv + m] = hh;
            g_vtl[dbase + (size_t)d * Nv + m] = ll;
        }
    }
}

// ---------------- split Wp into hi/lo -------------------------------------
__global__ void __launch_bounds__(256) split_wp_kernel(const float* __restrict__ Wp) {
    const int i = blockIdx.x * 256 + threadIdx.x;
    if (i < WPN) {
        __nv_bfloat16 hh, ll;
        split1(Wp[i], hh, ll);
        g_wph[i] = hh;
        g_wpl[i] = ll;
    }
}

// ---------------- cp.async helpers ----------------------------------------
__device__ __forceinline__ void cp16(void* dst, const void* src, int valid) {
    uint32_t s = (uint32_t)__cvta_generic_to_shared(dst);
    int sz = valid ? 16 : 0;
    asm volatile("cp.async.cg.shared.global [%0], [%1], 16, %2;\n"
                 :: "r"(s), "l"(src), "r"(sz));
}

__device__ __forceinline__ void mma_bf16(float* c, const uint32_t* a, const uint32_t* b) {
    asm volatile(
        "mma.sync.aligned.m16n8k16.row.col.f32.bf16.bf16.f32 "
        "{%0,%1,%2,%3}, {%4,%5,%6,%7}, {%8,%9}, {%0,%1,%2,%3};"
        : "+f"(c[0]), "+f"(c[1]), "+f"(c[2]), "+f"(c[3])
        : "r"(a[0]), "r"(a[1]), "r"(a[2]), "r"(a[3]), "r"(b[0]), "r"(b[1]));
}

#define LDSB 24   // smem row stride in bf16 (48B) — conflict-free frag loads

// ---------------- 128x128-tile bf16-split GEMM (QK / proj) ----------------
// 256 threads, 8 warps (2m x 4n), warp tile 64x32, BK=16, 2-stage cp.async.
// acc += Ah*Bh + Ah*Bl + Al*Bh ; C = acc (+bias[col])
__global__ void __launch_bounds__(256) mma4_plain_kernel(
        const __nv_bfloat16* __restrict__ Ah, const __nv_bfloat16* __restrict__ Al,
        const __nv_bfloat16* __restrict__ Bh, const __nv_bfloat16* __restrict__ Bl,
        float* __restrict__ C,
        int M, int Nn, int K, int lda, int ldb, int ldc,
        long sA, long sB, long sC, const float* __restrict__ bias) {
    extern __shared__ __nv_bfloat16 dsm4[];
    __nv_bfloat16 (*sm)[4][128][LDSB] = (__nv_bfloat16 (*)[4][128][LDSB])dsm4;

    const int z = blockIdx.z;
    Ah += (size_t)z * sA; Al += (size_t)z * sA;
    Bh += (size_t)z * sB; Bl += (size_t)z * sB;
    C  += (size_t)z * sC;
    const int m0 = blockIdx.y * 128, n0 = blockIdx.x * 128;
    const int tid  = threadIdx.x;
    const int warp = tid >> 5, lane = tid & 31;
    const int g = lane >> 2, t4 = lane & 3;
    const int wm = (warp & 1) * 64, wn = (warp >> 1) * 32;

    float acc[4][4][4];
    #pragma unroll
    for (int mf = 0; mf < 4; mf++)
        #pragma unroll
        for (int nf = 0; nf < 4; nf++)
            #pragma unroll
            for (int r = 0; r < 4; r++) acc[mf][nf][r] = 0.f;

    // loader: 1024 cp16 per stage over 256 threads
    const int nIter = K / 16;
    auto load_stage = [&](int stg, int kc) {
        #pragma unroll
        for (int i = 0; i < 4; i++) {
            const int idx = i * 256 + tid;
            const int arr = idx >> 8;            // 0 Ah, 1 Al, 2 Bh, 3 Bl
            const int rem = idx & 255;
            const int row = rem >> 1, hf = rem & 1;
            const __nv_bfloat16* base;
            int grow, valid, ld;
            if (arr < 2) {
                grow = m0 + row; valid = grow < M; ld = lda;
                base = arr ? Al : Ah;
            } else {
                grow = n0 + row; valid = grow < Nn; ld = ldb;
                base = (arr == 3) ? Bl : Bh;
            }
            const __nv_bfloat16* src = base + (size_t)(valid ? grow : 0) * ld + kc + hf * 8;
            cp16(&sm[stg][arr][row][hf * 8], src, valid);
        }
    };

    load_stage(0, 0);
    asm volatile("cp.async.commit_group;\n");

    for (int it = 0; it < nIter; it++) {
        asm volatile("cp.async.wait_group 0;\n");   // stage `it` ready
        __syncthreads();                            // prior readers of shared buffer done
        if (it + 1 < nIter) {
            load_stage((it + 1) & 1, (it + 1) * 16);
            asm volatile("cp.async.commit_group;\n");
        }

        const int st = it & 1;
        uint32_t aH[4][4], aL[4][4], bH[4][2], bL[4][2];
        #pragma unroll
        for (int mf = 0; mf < 4; mf++) {
            const int r0 = wm + mf * 16 + g;
            const uint32_t* h0 = (const uint32_t*)&sm[st][0][r0][0];
            const uint32_t* h1 = (const uint32_t*)&sm[st][0][r0 + 8][0];
            const uint32_t* l0 = (const uint32_t*)&sm[st][1][r0][0];
            const uint32_t* l1 = (const uint32_t*)&sm[st][1][r0 + 8][0];
            aH[mf][0] = h0[t4];     aH[mf][1] = h1[t4];
            aH[mf][2] = h0[t4 + 4]; aH[mf][3] = h1[t4 + 4];
            aL[mf][0] = l0[t4];     aL[mf][1] = l1[t4];
            aL[mf][2] = l0[t4 + 4]; aL[mf][3] = l1[t4 + 4];
        }
        #pragma unroll
        for (int nf = 0; nf < 4; nf++) {
            const int rb = wn + nf * 8 + g;
            const uint32_t* h = (const uint32_t*)&sm[st][2][rb][0];
            const uint32_t* l = (const uint32_t*)&sm[st][3][rb][0];
            bH[nf][0] = h[t4]; bH[nf][1] = h[t4 + 4];
            bL[nf][0] = l[t4]; bL[nf][1] = l[t4 + 4];
        }

        #pragma unroll
        for (int mf = 0; mf < 4; mf++)
            #pragma unroll
            for (int nf = 0; nf < 4; nf++)
                mma_bf16(acc[mf][nf], aH[mf], bH[nf]);
        #pragma unroll
        for (int mf = 0; mf < 4; mf++)
            #pragma unroll
            for (int nf = 0; nf < 4; nf++)
                mma_bf16(acc[mf][nf], aH[mf], bL[nf]);
        #pragma unroll
        for (int mf = 0; mf < 4; mf++)
            #pragma unroll
            for (int nf = 0; nf < 4; nf++)
                mma_bf16(acc[mf][nf], aL[mf], bH[nf]);
    }

    #pragma unroll
    for (int mf = 0; mf < 4; mf++) {
        #pragma unroll
        for (int nf = 0; nf < 4; nf++) {
            const int col = n0 + wn + nf * 8 + 2 * t4;
            if (col >= Nn) continue;
            float bx = 0.f, by = 0.f;
            if (bias) {
                const float2 bb = *(const float2*)(bias + col);
                bx = bb.x; by = bb.y;
            }
            const int r0 = m0 + wm + mf * 16 + g;
            if (r0 < M) {
                float2 vv; vv.x = acc[mf][nf][0] + bx; vv.y = acc[mf][nf][1] + by;
                *(float2*)(C + (size_t)r0 * ldc + col) = vv;
            }
            const int r1 = r0 + 8;
            if (r1 < M) {
                float2 vv; vv.x = acc[mf][nf][2] + bx; vv.y = acc[mf][nf][3] + by;
                *(float2*)(C + (size_t)r1 * ldc + col) = vv;
            }
        }
    }
}
#define MMA4_SMEM (2 * 4 * 128 * LDSB * 2)   // 49152 bytes

// ---------------- AV GEMM, 64x96 tile, 192 threads (6 warps, 2m x 3n) -----
__global__ void __launch_bounds__(192) mma3_av_kernel() {
    __shared__ __align__(16) __nv_bfloat16 smA[3][2][64][LDSB];
    __shared__ __align__(16) __nv_bfloat16 smB[3][2][96][LDSB];
    const int z = blockIdx.z;                    // bh = b*8 + o
    const __nv_bfloat16* Ah = g_a2h + (size_t)z * NNv;
    const __nv_bfloat16* Al = g_a2l + (size_t)z * NNv;
    const __nv_bfloat16* Bh = g_vth + (size_t)z * Dv * Nv;
    const __nv_bfloat16* Bl = g_vtl + (size_t)z * Dv * Nv;
    const int m0 = blockIdx.y * 64;
    const int tid = threadIdx.x;
    const int warp = tid >> 5, lane = tid & 31;
    const int g = lane >> 2, t4 = lane & 3;
    const int wm = (warp & 1) * 32, wn = (warp >> 1) * 32;   // wn in {0,32,64}

    float acc[2][4][4];
    #pragma unroll
    for (int mf = 0; mf < 2; mf++)
        #pragma unroll
        for (int nf = 0; nf < 4; nf++)
            #pragma unroll
            for (int r = 0; r < 4; r++) acc[mf][nf][r] = 0.f;

    const int nIter = Nv / 16;    // 49

    auto load_stage = [&](int stg, int kc) {
        #pragma unroll
        for (int i = 0; i < 4; i++) {
            const int idx = i * 192 + tid;
            if (idx >= 640) break;
            if (idx < 256) {
                const int part = idx >> 7;
                const int rem  = idx & 127;
                const int row  = rem >> 1, hf = rem & 1;
                const int grow = m0 + row;
                const int valid = grow < Nv;
                const __nv_bfloat16* src =
                    (part ? Al : Ah) + (size_t)(valid ? grow : 0) * Nv + kc + hf * 8;
                cp16(&smA[stg][part][row][hf * 8], src, valid);
            } else {
                const int j = idx - 256;
                const int part = j >= 192;
                const int rem  = part ? (j - 192) : j;
                const int row  = rem >> 1, hf = rem & 1;
                const __nv_bfloat16* src =
                    (part ? Bl : Bh) + (size_t)row * Nv + kc + hf * 8;
                cp16(&smB[stg][part][row][hf * 8], src, 1);
            }
        }
    };

    load_stage(0, 0);
    asm volatile("cp.async.commit_group;\n");
    load_stage(1, 16);
    asm volatile("cp.async.commit_group;\n");

    int st = 0, wst = 2;
    for (int it = 0; it < nIter; it++) {
        if (it + 1 < nIter) {
            asm volatile("cp.async.wait_group 1;\n");
        } else {
            asm volatile("cp.async.wait_group 0;\n");
        }
        __syncthreads();

        if (it + 2 < nIter) {
            load_stage(wst, (it + 2) * 16);
            asm volatile("cp.async.commit_group;\n");
            wst = (wst == 2) ? 0 : wst + 1;
        }

        uint32_t aH[2][4], aL[2][4], bH[4][2], bL[4][2];
        #pragma unroll
        for (int mf = 0; mf < 2; mf++) {
            const int r0 = wm + mf * 16 + g;
            const uint32_t* h0 = (const uint32_t*)&smA[st][0][r0][0];
            const uint32_t* h1 = (const uint32_t*)&smA[st][0][r0 + 8][0];
            const uint32_t* l0 = (const uint32_t*)&smA[st][1][r0][0];
            const uint32_t* l1 = (const uint32_t*)&smA[st][1][r0 + 8][0];
            aH[mf][0] = h0[t4];     aH[mf][1] = h1[t4];
            aH[mf][2] = h0[t4 + 4]; aH[mf][3] = h1[t4 + 4];
            aL[mf][0] = l0[t4];     aL[mf][1] = l1[t4];
            aL[mf][2] = l0[t4 + 4]; aL[mf][3] = l1[t4 + 4];
        }
        #pragma unroll
        for (int nf = 0; nf < 4; nf++) {
            const int rb = wn + nf * 8 + g;
            const uint32_t* h = (const uint32_t*)&smB[st][0][rb][0];
            const uint32_t* l = (const uint32_t*)&smB[st][1][rb][0];
            bH[nf][0] = h[t4]; bH[nf][1] = h[t4 + 4];
            bL[nf][0] = l[t4]; bL[nf][1] = l[t4 + 4];
        }
        st = (st == 2) ? 0 : st + 1;

        #pragma unroll
        for (int mf = 0; mf < 2; mf++)
            #pragma unroll
            for (int nf = 0; nf < 4; nf++)
                mma_bf16(acc[mf][nf], aH[mf], bH[nf]);
        #pragma unroll
        for (int mf = 0; mf < 2; mf++)
            #pragma unroll
            for (int nf = 0; nf < 4; nf++)
                mma_bf16(acc[mf][nf], aH[mf], bL[nf]);
        #pragma unroll
        for (int mf = 0; mf < 2; mf++)
            #pragma unroll
            for (int nf = 0; nf < 4; nf++)
                mma_bf16(acc[mf][nf], aL[mf], bH[nf]);
    }

    // epilogue: BN affine + colsum, split-write into xcat
    const int b = z >> 3, o = z & 7;
    const float a_s = g_bn[o];
    const float c_s = g_bn[8 + o];
    const size_t xbase = (size_t)b * Nv * Cv + o * Dv;
    #pragma unroll
    for (int mf = 0; mf < 2; mf++) {
        #pragma unroll
        for (int nf = 0; nf < 4; nf++) {
            const int col = wn + nf * 8 + 2 * t4;       // 0..94, always < 96
            const float cxs = c_s * g_colsum[z * Dv + col];
            const float cys = c_s * g_colsum[z * Dv + col + 1];
            const int r0 = m0 + wm + mf * 16 + g;
            if (r0 < Nv) {
                uint32_t hi, lo;
                split2(a_s * acc[mf][nf][0] + cxs, a_s * acc[mf][nf][1] + cys, hi, lo);
                *(uint32_t*)(g_xch + xbase + (size_t)r0 * Cv + col) = hi;
                *(uint32_t*)(g_xcl + xbase + (size_t)r0 * Cv + col) = lo;
            }
            const int r1 = r0 + 8;
            if (r1 < Nv) {
                uint32_t hi, lo;
                split2(a_s * acc[mf][nf][2] + cxs, a_s * acc[mf][nf][3] + cys, hi, lo);
                *(uint32_t*)(g_xch + xbase + (size_t)r1 * Cv + col) = hi;
                *(uint32_t*)(g_xcl + xbase + (size_t)r1 * Cv + col) = lo;
            }
        }
    }
}

// ---------------- fused softmax + cross-head mix + BN stats ---------------
// mix loop handles adjacent m-pairs -> packed uint32 stores per plane
__global__ void __launch_bounds__(256) softmax_mix_stats_kernel(
        const float* __restrict__ Wre,
        const float* __restrict__ bre) {
    __shared__ float smx[8][Nv];
    __shared__ float sW[64];
    __shared__ float sb[8];
    __shared__ float part[8][16];
    const int bn  = blockIdx.x;           // b*Nv + n
    const int b   = bn / Nv, n = bn % Nv;
    const int tid = threadIdx.x;
    const int w   = tid >> 5, lane = tid & 31;
    if (tid < 64) sW[tid] = Wre[tid];
    if (tid < 8)  sb[tid] = bre[tid];

    // warp-per-head softmax
    const float* src = g_attn + ((size_t)(b * 8 + w) * Nv + n) * Nv;
    float lmax = -1e30f;
    for (int i = lane; i < Nv; i += 32) {
        const float vv = src[i];
        smx[w][i] = vv;
        lmax = fmaxf(lmax, vv);
    }
    #pragma unroll
    for (int s = 16; s; s >>= 1) lmax = fmaxf(lmax, __shfl_xor_sync(0xffffffffu, lmax, s));
    float lsum = 0.f;
    for (int i = lane; i < Nv; i += 32) {
        const float e = __expf(smx[w][i] - lmax);
        smx[w][i] = e;
        lsum += e;
    }
    #pragma unroll
    for (int s = 16; s; s >>= 1) lsum += __shfl_xor_sync(0xffffffffu, lsum, s);
    const float inv = 1.f / lsum;
    for (int i = lane; i < Nv; i += 32) smx[w][i] *= inv;
    __syncthreads();

    // per-thread analytic means
    float mu[8];
    #pragma unroll
    for (int o = 0; o < 8; o++) {
        float s = 0.f;
        #pragma unroll
        for (int h = 0; h < 8; h++) s += sW[o * 8 + h];
        mu[o] = s * (1.0f / (float)Nv) + sb[o];
    }

    // mix + stats + packed split-write (m pairs)
    const size_t obase = (size_t)b * Hv * NNv + (size_t)n * Nv;
    float sd[8], sq[8];
    #pragma unroll
    for (int o = 0; o < 8; o++) { sd[o] = 0.f; sq[o] = 0.f; }
    for (int mp = tid; mp < Nv / 2; mp += 256) {
        const int m = mp * 2;
        float p0[8], p1[8];
        #pragma unroll
        for (int h = 0; h < 8; h++) { p0[h] = smx[h][m]; p1[h] = smx[h][m + 1]; }
        #pragma unroll
        for (int o = 0; o < 8; o++) {
            float a0 = sb[o], a1 = sb[o];
            #pragma unroll
            for (int h = 0; h < 8; h++) {
                a0 += sW[o * 8 + h] * p0[h];
                a1 += sW[o * 8 + h] * p1[h];
            }
            uint32_t hi, lo;
            split2(a0, a1, hi, lo);
            *(uint32_t*)(g_a2h + obase + (size_t)o * NNv + m) = hi;
            *(uint32_t*)(g_a2l + obase + (size_t)o * NNv + m) = lo;
            const float d0 = a0 - mu[o];
            const float d1 = a1 - mu[o];
            sd[o] += d0 + d1;
            sq[o] += d0 * d0 + d1 * d1;
        }
    }
    #pragma unroll
    for (int o = 0; o < 8; o++) {
        #pragma unroll
        for (int s = 16; s; s >>= 1) {
            sd[o] += __shfl_xor_sync(0xffffffffu, sd[o], s);
            sq[o] += __shfl_xor_sync(0xffffffffu, sq[o], s);
        }
    }
    if (lane == 0) {
        #pragma unroll
        for (int o = 0; o < 8; o++) {
            part[w][o]     = sd[o];
            part[w][8 + o] = sq[o];
        }
    }
    __syncthreads();
    if (tid < 16) {
        float s = 0.f;
        #pragma unroll
        for (int ww = 0; ww < 8; ww++) s += part[ww][tid];
        atomicAdd(&g_stats[tid], (double)s);
    }
}

// ---------------- finalize BN scalars -------------------------------------
__global__ void bn_finalize_kernel(const float* __restrict__ Wre,
                                   const float* __restrict__ bre,
                                   const float* __restrict__ gamma,
                                   const float* __restrict__ beta) {
    const int o = threadIdx.x;
    if (o >= 8) return;
    const double cnt = (double)BNNv;
    float s = 0.f;
    #pragma unroll
    for (int h = 0; h < 8; h++) s += Wre[o * 8 + h];
    const double mu   = (double)s / (double)Nv + (double)bre[o];
    const double sd   = g_stats[o];
    const double sq   = g_stats[8 + o];
    const double mean = mu + sd / cnt;
    const double var  = sq / cnt - (sd / cnt) * (sd / cnt);
    const float a = gamma[o] * (float)(1.0 / sqrt(var + (double)BN_EPS));
    const float c = beta[o] - a * (float)mean;
    g_bn[o]     = a;
    g_bn[8 + o] = c;
}

// ---------------- launch ---------------------------------------------------
extern "C" void kernel_launch(void* const* d_in, const int* in_sizes, int n_in,
                              void* d_out, int out_size) {
    const float* q     = (const float*)d_in[0];
    const float* k     = (const float*)d_in[1];
    const float* v     = (const float*)d_in[2];
    const float* Wq    = (const float*)d_in[3];
    const float* Wk    = (const float*)d_in[4];
    const float* Wv    = (const float*)d_in[5];
    const float* Wre   = (const float*)d_in[6];
    const float* bre   = (const float*)d_in[7];
    const float* gamma = (const float*)d_in[8];
    const float* beta  = (const float*)d_in[9];
    const float* Wp    = (const float*)d_in[10];
    const float* bp    = (const float*)d_in[11];
    float* out = (float*)d_out;

    void *pqhh, *pqhl, *pkhh, *pkhl, *pattn, *pxch, *pxcl, *pwph, *pwpl;
    cudaGetSymbolAddress(&pqhh,  g_qhh);
    cudaGetSymbolAddress(&pqhl,  g_qhl);
    cudaGetSymbolAddress(&pkhh,  g_khh);
    cudaGetSymbolAddress(&pkhl,  g_khl);
    cudaGetSymbolAddress(&pattn, g_attn);
    cudaGetSymbolAddress(&pxch,  g_xch);
    cudaGetSymbolAddress(&pxcl,  g_xcl);
    cudaGetSymbolAddress(&pwph,  g_wph);
    cudaGetSymbolAddress(&pwpl,  g_wpl);

    cudaFuncSetAttribute(mma4_plain_kernel,
                         cudaFuncAttributeMaxDynamicSharedMemorySize, MMA4_SMEM);

    zero_stats_kernel<<<1, 32>>>();
    conv_qkv_kernel<<<dim3(Bv * Nv, 3), 256>>>(q, k, v, Wq, Wk, Wv);
    colsum_v_kernel<<<Bv * Hv, 384>>>();
    transpose_v_kernel<<<dim3(25, 3, 64), dim3(32, 8)>>>();
    split_wp_kernel<<<(WPN + 255) / 256, 256>>>(Wp);

    // S = Qs Kh^T (scale folded into Q), batched over B*H — 128x128 tiles
    mma4_plain_kernel<<<dim3(7, 7, Bv * Hv), 256, MMA4_SMEM>>>(
        (const __nv_bfloat16*)pqhh, (const __nv_bfloat16*)pqhl,
        (const __nv_bfloat16*)pkhh, (const __nv_bfloat16*)pkhl,
        (float*)pattn,
        Nv, Nv, Dv, Dv, Dv, Nv,
        (long)Nv * Dv, (long)Nv * Dv, (long)NNv,
        nullptr);

    softmax_mix_stats_kernel<<<Bv * Nv, 256>>>(Wre, bre);
    bn_finalize_kernel<<<1, 8>>>(Wre, bre, gamma, beta);

    // AV: per (b,o): xcat <- a_o*(A @ V) + c_o*colsum (96-wide tile, split-write)
    mma3_av_kernel<<<dim3(1, 13, Bv * Hv), 192>>>();

    // out = xcat @ Wp^T + bp — 128x128 tiles
    mma4_plain_kernel<<<dim3(6, 49, 1), 256, MMA4_SMEM>>>(
        (const __nv_bfloat16*)pxch, (const __nv_bfloat16*)pxcl,
        (const __nv_bfloat16*)pwph, (const __nv_bfloat16*)pwpl,
        out,
        Bv * Nv, Cv, Cv, Cv, Cv, Cv,
        0L, 0L, 0L,
        bp);
}